// round 2
// baseline (speedup 1.0000x reference)
#include <cuda_runtime.h>

#define L_SEQ 2048
#define DM 1024
#define HD 64
#define NG 32            // b * n_head after buggy reshape = 2*16
#define MTOT 4096        // B * L

// Scratch (static device globals -- no allocation allowed)
__device__ float g_qp[MTOT * DM];
__device__ float g_kp[MTOT * DM];
__device__ float g_vp[MTOT * DM];
__device__ float g_ctx[MTOT * DM];
__device__ float g_sv[NG * (L_SEQ + 1) * HD];   // suffix sums of V per head
__device__ float g_csum[NG * 8 * HD];

// ---------------------------------------------------------------------------
// C[m,n] = sum_k A[m,k] * Bw[n,k] + bias[n]   (NT GEMM with bias)
// 128x128 tile, BK=16, 256 threads, 8x8 microtile
// ---------------------------------------------------------------------------
__global__ __launch_bounds__(256) void gemm_nt_bias(
    const float* __restrict__ A, const float* __restrict__ Bw,
    const float* __restrict__ bias, float* __restrict__ C,
    int M, int N, int K)
{
    __shared__ float As[16][128];
    __shared__ float Bs[16][128];
    const int t  = threadIdx.x;
    const int tx = t & 15, ty = t >> 4;          // 16x16 thread grid
    const int bm = blockIdx.x * 128, bn = blockIdx.y * 128;

    const int lr = t >> 1;            // 0..127 row within tile
    const int lc = (t & 1) * 8;       // 0 or 8: k offset

    float acc[8][8] = {};

    for (int k0 = 0; k0 < K; k0 += 16) {
        float4 a0 = *(const float4*)&A [(size_t)(bm + lr) * K + k0 + lc];
        float4 a1 = *(const float4*)&A [(size_t)(bm + lr) * K + k0 + lc + 4];
        float4 b0 = *(const float4*)&Bw[(size_t)(bn + lr) * K + k0 + lc];
        float4 b1 = *(const float4*)&Bw[(size_t)(bn + lr) * K + k0 + lc + 4];
        As[lc+0][lr]=a0.x; As[lc+1][lr]=a0.y; As[lc+2][lr]=a0.z; As[lc+3][lr]=a0.w;
        As[lc+4][lr]=a1.x; As[lc+5][lr]=a1.y; As[lc+6][lr]=a1.z; As[lc+7][lr]=a1.w;
        Bs[lc+0][lr]=b0.x; Bs[lc+1][lr]=b0.y; Bs[lc+2][lr]=b0.z; Bs[lc+3][lr]=b0.w;
        Bs[lc+4][lr]=b1.x; Bs[lc+5][lr]=b1.y; Bs[lc+6][lr]=b1.z; Bs[lc+7][lr]=b1.w;
        __syncthreads();
        #pragma unroll
        for (int k = 0; k < 16; k++) {
            float4 av0 = *(const float4*)&As[k][ty*8];
            float4 av1 = *(const float4*)&As[k][ty*8+4];
            float4 bv0 = *(const float4*)&Bs[k][tx*8];
            float4 bv1 = *(const float4*)&Bs[k][tx*8+4];
            float am[8] = {av0.x,av0.y,av0.z,av0.w, av1.x,av1.y,av1.z,av1.w};
            float bb[8] = {bv0.x,bv0.y,bv0.z,bv0.w, bv1.x,bv1.y,bv1.z,bv1.w};
            #pragma unroll
            for (int i = 0; i < 8; i++)
                #pragma unroll
                for (int j = 0; j < 8; j++)
                    acc[i][j] += am[i] * bb[j];
        }
        __syncthreads();
    }

    float4 bl = *(const float4*)&bias[bn + tx*8];
    float4 bh = *(const float4*)&bias[bn + tx*8 + 4];
    float bv[8] = {bl.x,bl.y,bl.z,bl.w, bh.x,bh.y,bh.z,bh.w};
    #pragma unroll
    for (int i = 0; i < 8; i++) {
        float* crow = &C[(size_t)(bm + ty*8 + i) * N + bn + tx*8];
        float4 o0, o1;
        o0.x = acc[i][0] + bv[0]; o0.y = acc[i][1] + bv[1];
        o0.z = acc[i][2] + bv[2]; o0.w = acc[i][3] + bv[3];
        o1.x = acc[i][4] + bv[4]; o1.y = acc[i][5] + bv[5];
        o1.z = acc[i][6] + bv[6]; o1.w = acc[i][7] + bv[7];
        *(float4*)&crow[0] = o0;
        *(float4*)&crow[4] = o1;
    }
}

// ---------------------------------------------------------------------------
// Suffix sums of V per head: sv[g][i][d] = sum_{j>=i} vp[g][j][d], sv[g][L]=0
// ---------------------------------------------------------------------------
__global__ void sfx1(const float* __restrict__ vp, float* __restrict__ sv,
                     float* __restrict__ csum)
{
    int g = blockIdx.x;     // 0..31
    int c = blockIdx.y;     // 0..7  (chunks of 256 rows)
    int d = threadIdx.x;    // 0..63
    const float* v = vp + (size_t)g * L_SEQ * HD;
    float* s = sv + (size_t)g * (L_SEQ + 1) * HD;
    float a = 0.f;
    #pragma unroll 8
    for (int j = (c + 1) * 256 - 1; j >= c * 256; j--) {
        a += v[j * HD + d];
        s[j * HD + d] = a;
    }
    csum[(g * 8 + c) * HD + d] = a;
}

__global__ void sfx2(float* __restrict__ sv, const float* __restrict__ csum)
{
    int g = blockIdx.x;
    int c = blockIdx.y;
    int d = threadIdx.x;
    float* s = sv + (size_t)g * (L_SEQ + 1) * HD;
    if (c == 7) {
        s[L_SEQ * HD + d] = 0.f;
        return;                      // no later chunks -> offset is exactly 0
    }
    float off = 0.f;
    for (int c2 = c + 1; c2 < 8; c2++) off += csum[(g * 8 + c2) * HD + d];
    #pragma unroll 8
    for (int j = c * 256; j < (c + 1) * 256; j++)
        s[j * HD + d] += off;
}

// ---------------------------------------------------------------------------
// Attention over reinterpreted heads [NG, L, HD].
// Causal-only score compute + online softmax; the zero-block (scores set to 0
// above the diagonal, which still participate in softmax) is folded in at the
// end via suffix sums:   ctx_i = (Sum_{j<=i} e^{s-m'} v_j + e^{-m'} SV[i+1])/Z
// ---------------------------------------------------------------------------
__global__ __launch_bounds__(256) void attn_kernel(
    const float* __restrict__ qp, const float* __restrict__ kp,
    const float* __restrict__ vp, const float* __restrict__ sv,
    float* __restrict__ ctx)
{
    const int g  = blockIdx.y;      // head 0..31
    const int qi = blockIdx.x;      // q tile 0..31
    const int i0 = qi * 64;
    const float* Qh = qp + (size_t)g * L_SEQ * HD;
    const float* Kh = kp + (size_t)g * L_SEQ * HD;
    const float* Vh = vp + (size_t)g * L_SEQ * HD;

    __shared__ float Qs[64][68];
    __shared__ float Ks[32][68];
    __shared__ float Vs[32][68];
    __shared__ float Ss[64][36];
    __shared__ float row_m[64], row_l[64], row_a[64], row_b[64];

    const int t  = threadIdx.x;
    const int tx = t & 15, ty = t >> 4;

    // load Q tile (64x64)
    #pragma unroll
    for (int rep = 0; rep < 4; rep++) {
        int idx = t + rep * 256;
        int r = idx >> 4, c4 = (idx & 15) * 4;
        *(float4*)&Qs[r][c4] = *(const float4*)&Qh[(size_t)(i0 + r) * HD + c4];
    }
    if (t < 64) { row_m[t] = -1e30f; row_l[t] = 0.f; }
    float acc[4][4] = {};
    __syncthreads();

    const int num_kb = qi * 2 + 2;   // key tiles needed to cover j <= i0+63
    for (int kb = 0; kb < num_kb; kb++) {
        const int j0 = kb * 32;
        #pragma unroll
        for (int rep = 0; rep < 2; rep++) {
            int idx = t + rep * 256;
            int r = idx >> 4, c4 = (idx & 15) * 4;
            *(float4*)&Ks[r][c4] = *(const float4*)&Kh[(size_t)(j0 + r) * HD + c4];
            *(float4*)&Vs[r][c4] = *(const float4*)&Vh[(size_t)(j0 + r) * HD + c4];
        }
        __syncthreads();

        // S tile: rows ty*4..+3 (of 64), cols tx*2..+1 (of 32)
        float s[4][2] = {};
        #pragma unroll
        for (int k4 = 0; k4 < 16; k4++) {
            float4 k0v = *(const float4*)&Ks[tx*2+0][k4*4];
            float4 k1v = *(const float4*)&Ks[tx*2+1][k4*4];
            #pragma unroll
            for (int i = 0; i < 4; i++) {
                float4 qv = *(const float4*)&Qs[ty*4+i][k4*4];
                s[i][0] += qv.x*k0v.x + qv.y*k0v.y + qv.z*k0v.z + qv.w*k0v.w;
                s[i][1] += qv.x*k1v.x + qv.y*k1v.y + qv.z*k1v.z + qv.w*k1v.w;
            }
        }
        #pragma unroll
        for (int i = 0; i < 4; i++) {
            int gi = i0 + ty*4 + i;
            #pragma unroll
            for (int c = 0; c < 2; c++) {
                int gj = j0 + tx*2 + c;
                Ss[ty*4+i][tx*2+c] = (gj > gi) ? -1e30f : s[i][c] * 0.125f;
            }
        }
        __syncthreads();

        // online softmax bookkeeping (one thread per row)
        if (t < 64) {
            float m_old = row_m[t];
            float m = m_old;
            #pragma unroll
            for (int c = 0; c < 32; c++) m = fmaxf(m, Ss[t][c]);
            float scale = __expf(m_old - m);
            float lsum = 0.f;
            #pragma unroll
            for (int c = 0; c < 32; c++) {
                float p = __expf(Ss[t][c] - m);
                Ss[t][c] = p;
                lsum += p;
            }
            row_m[t] = m;
            row_l[t] = row_l[t] * scale + lsum;
            row_a[t] = scale;
        }
        __syncthreads();

        // rescale accumulator, then acc += P(64x32) @ V(32x64)
        float rs[4];
        #pragma unroll
        for (int i = 0; i < 4; i++) rs[i] = row_a[ty*4+i];
        #pragma unroll
        for (int i = 0; i < 4; i++)
            #pragma unroll
            for (int j = 0; j < 4; j++) acc[i][j] *= rs[i];

        #pragma unroll
        for (int kk4 = 0; kk4 < 8; kk4++) {
            float pr[4][4];
            #pragma unroll
            for (int i = 0; i < 4; i++) {
                float4 p4 = *(const float4*)&Ss[ty*4+i][kk4*4];
                pr[i][0]=p4.x; pr[i][1]=p4.y; pr[i][2]=p4.z; pr[i][3]=p4.w;
            }
            #pragma unroll
            for (int c = 0; c < 4; c++) {
                float4 vv = *(const float4*)&Vs[kk4*4+c][tx*4];
                float vm[4] = {vv.x, vv.y, vv.z, vv.w};
                #pragma unroll
                for (int i = 0; i < 4; i++)
                    #pragma unroll
                    for (int j = 0; j < 4; j++)
                        acc[i][j] += pr[i][c] * vm[j];
            }
        }
        __syncthreads();
    }

    // fold in the zero-block (zeros above diagonal participate in softmax)
    if (t < 64) {
        float m = row_m[t], l = row_l[t];
        float mf = fmaxf(m, 0.f);
        int ig = i0 + t;
        float cnt = (float)(L_SEQ - 1 - ig);
        float ez = __expf(-mf);
        float sc = __expf(m - mf);
        float lf = l * sc + cnt * ez;
        row_a[t] = sc;
        row_b[t] = ez;
        row_l[t] = 1.f / lf;
    }
    __syncthreads();

    const float* svg = sv + (size_t)g * (L_SEQ + 1) * HD;
    float* ctxg = ctx + (size_t)g * L_SEQ * HD;
    #pragma unroll
    for (int i = 0; i < 4; i++) {
        int r = ty*4 + i;
        int ig = i0 + r;
        float scf = row_a[r], ez = row_b[r], inv = row_l[r];
        float4 svv = *(const float4*)&svg[(size_t)(ig + 1) * HD + tx*4];
        float4 o;
        o.x = (acc[i][0]*scf + ez*svv.x) * inv;
        o.y = (acc[i][1]*scf + ez*svv.y) * inv;
        o.z = (acc[i][2]*scf + ez*svv.z) * inv;
        o.w = (acc[i][3]*scf + ez*svv.w) * inv;
        *(float4*)&ctxg[(size_t)ig * HD + tx*4] = o;
    }
}

// ---------------------------------------------------------------------------
extern "C" void kernel_launch(void* const* d_in, const int* in_sizes, int n_in,
                              void* d_out, int out_size)
{
    const float* q     = (const float*)d_in[0];
    const float* k     = (const float*)d_in[1];
    const float* v     = (const float*)d_in[2];
    // d_in[3] = attn_mask (causal by construction; handled analytically)
    const float* wq_w  = (const float*)d_in[4];
    const float* wq_b  = (const float*)d_in[5];
    const float* out_w = (const float*)d_in[6];
    const float* out_b = (const float*)d_in[7];
    float* out = (float*)d_out;

    float *qp, *kp, *vp, *ctx, *sv, *csum;
    cudaGetSymbolAddress((void**)&qp,   g_qp);
    cudaGetSymbolAddress((void**)&kp,   g_kp);
    cudaGetSymbolAddress((void**)&vp,   g_vp);
    cudaGetSymbolAddress((void**)&ctx,  g_ctx);
    cudaGetSymbolAddress((void**)&sv,   g_sv);
    cudaGetSymbolAddress((void**)&csum, g_csum);

    dim3 gg(MTOT / 128, DM / 128);
    gemm_nt_bias<<<gg, 256>>>(q, wq_w, wq_b, qp, MTOT, DM, DM);
    gemm_nt_bias<<<gg, 256>>>(k, wq_w, wq_b, kp, MTOT, DM, DM);
    gemm_nt_bias<<<gg, 256>>>(v, wq_w, wq_b, vp, MTOT, DM, DM);
    sfx1<<<dim3(NG, 8), HD>>>(vp, sv, csum);
    sfx2<<<dim3(NG, 8), HD>>>(sv, csum);
    attn_kernel<<<dim3(L_SEQ / 64, NG), 256>>>(qp, kp, vp, sv, ctx);
    gemm_nt_bias<<<gg, 256>>>(ctx, out_w, out_b, out, MTOT, DM, DM);
}

// round 3
// speedup vs baseline: 1.0396x; 1.0396x over previous
#include <cuda_runtime.h>

#define L_SEQ 2048
#define DM 1024
#define HD 64
#define NG 32            // b * n_head after buggy reshape = 2*16
#define MTOT 4096        // B * L

// Scratch (static device globals -- no allocation allowed)
__device__ float g_qp[MTOT * DM];
__device__ float g_kp[MTOT * DM];
__device__ float g_vp[MTOT * DM];
__device__ float g_ctx[MTOT * DM];
__device__ float g_sv[NG * (L_SEQ + 1) * HD];   // suffix sums of V per head
__device__ float g_csum[NG * 8 * HD];

// ---------------------------------------------------------------------------
// Tensor-core NT GEMM with bias, 3xTF32 precision recovery.
// C[m,n] = sum_k A[m,k]*Bw[n,k] + bias[n]
// CTA tile 128x128, BK=16, 256 threads (8 warps, 2x4 grid, 64x32 warp tiles)
// A/B split into tf32 hi/lo; D += Ah*Bh + Ah*Bl + Al*Bh  (err ~ 2^-22)
// ---------------------------------------------------------------------------
#define MMA8(d, a, b) asm volatile( \
  "mma.sync.aligned.m16n8k8.row.col.f32.tf32.tf32.f32 " \
  "{%0,%1,%2,%3}, {%4,%5,%6,%7}, {%8,%9}, {%0,%1,%2,%3};\n" \
  : "+f"(d[0]), "+f"(d[1]), "+f"(d[2]), "+f"(d[3]) \
  : "r"(a[0]), "r"(a[1]), "r"(a[2]), "r"(a[3]), "r"(b[0]), "r"(b[1]))

__device__ __forceinline__ void split_tf32(float x, unsigned& hi, unsigned& lo)
{
    asm("cvt.rna.tf32.f32 %0, %1;" : "=r"(hi) : "f"(x));
    float r = x - __uint_as_float(hi);
    asm("cvt.rna.tf32.f32 %0, %1;" : "=r"(lo) : "f"(r));
}

__global__ __launch_bounds__(256) void gemm_tf32_bias(
    const float* __restrict__ A, const float* __restrict__ Bw,
    const float* __restrict__ bias, float* __restrict__ C,
    int M, int N, int K)
{
    __shared__ unsigned Ah[16][136], Al[16][136], Bh[16][136], Bl[16][136];

    const int t    = threadIdx.x;
    const int lane = t & 31;
    const int warp = t >> 5;
    const int g    = lane >> 2;    // groupID 0..7
    const int tg   = lane & 3;     // thread-in-group 0..3
    const int wm   = warp >> 2;    // 0..1
    const int wn   = warp & 3;     // 0..3
    const int bm   = blockIdx.x * 128, bn = blockIdx.y * 128;

    const int lr = t >> 1;         // 0..127 tile row for global loads
    const int lc = (t & 1) * 8;    // k offset 0 or 8

    float acc[4][4][4] = {};       // [mtile][ntile][creg]

    const float* Arow = &A [(size_t)(bm + lr) * K + lc];
    const float* Brow = &Bw[(size_t)(bn + lr) * K + lc];

    float4 pa0 = *(const float4*)&Arow[0];
    float4 pa1 = *(const float4*)&Arow[4];
    float4 pb0 = *(const float4*)&Brow[0];
    float4 pb1 = *(const float4*)&Brow[4];

    const int KT = K / 16;
    for (int kt = 0; kt < KT; kt++) {
        // stage current prefetch into smem (hi/lo split)
        {
            float av[8] = {pa0.x,pa0.y,pa0.z,pa0.w, pa1.x,pa1.y,pa1.z,pa1.w};
            float bv[8] = {pb0.x,pb0.y,pb0.z,pb0.w, pb1.x,pb1.y,pb1.z,pb1.w};
            #pragma unroll
            for (int j = 0; j < 8; j++) {
                unsigned h, l;
                split_tf32(av[j], h, l);
                Ah[lc + j][lr] = h;  Al[lc + j][lr] = l;
                split_tf32(bv[j], h, l);
                Bh[lc + j][lr] = h;  Bl[lc + j][lr] = l;
            }
        }
        __syncthreads();

        // prefetch next k-slab while computing
        if (kt + 1 < KT) {
            const float* An = Arow + (kt + 1) * 16;
            const float* Bn = Brow + (kt + 1) * 16;
            pa0 = *(const float4*)&An[0];
            pa1 = *(const float4*)&An[4];
            pb0 = *(const float4*)&Bn[0];
            pb1 = *(const float4*)&Bn[4];
        }

        #pragma unroll
        for (int ks = 0; ks < 16; ks += 8) {
            unsigned ah[4][4], al[4][4], bh[4][2], bl[4][2];
            #pragma unroll
            for (int mt = 0; mt < 4; mt++) {
                int r = wm * 64 + mt * 16 + g;
                ah[mt][0] = Ah[ks+tg  ][r];   al[mt][0] = Al[ks+tg  ][r];
                ah[mt][1] = Ah[ks+tg  ][r+8]; al[mt][1] = Al[ks+tg  ][r+8];
                ah[mt][2] = Ah[ks+tg+4][r];   al[mt][2] = Al[ks+tg+4][r];
                ah[mt][3] = Ah[ks+tg+4][r+8]; al[mt][3] = Al[ks+tg+4][r+8];
            }
            #pragma unroll
            for (int nt = 0; nt < 4; nt++) {
                int c = wn * 32 + nt * 8 + g;
                bh[nt][0] = Bh[ks+tg  ][c];   bl[nt][0] = Bl[ks+tg  ][c];
                bh[nt][1] = Bh[ks+tg+4][c];   bl[nt][1] = Bl[ks+tg+4][c];
            }
            #pragma unroll
            for (int mt = 0; mt < 4; mt++)
                #pragma unroll
                for (int nt = 0; nt < 4; nt++) {
                    MMA8(acc[mt][nt], ah[mt], bh[nt]);
                    MMA8(acc[mt][nt], ah[mt], bl[nt]);
                    MMA8(acc[mt][nt], al[mt], bh[nt]);
                }
        }
        __syncthreads();
    }

    // epilogue with bias
    #pragma unroll
    for (int mt = 0; mt < 4; mt++) {
        int row = bm + wm * 64 + mt * 16 + g;
        #pragma unroll
        for (int nt = 0; nt < 4; nt++) {
            int col = bn + wn * 32 + nt * 8 + tg * 2;
            float2 b2 = *(const float2*)&bias[col];
            float2 o0 = {acc[mt][nt][0] + b2.x, acc[mt][nt][1] + b2.y};
            float2 o1 = {acc[mt][nt][2] + b2.x, acc[mt][nt][3] + b2.y};
            *(float2*)&C[(size_t)row * N + col]       = o0;
            *(float2*)&C[(size_t)(row + 8) * N + col] = o1;
        }
    }
}

// ---------------------------------------------------------------------------
// Suffix sums of V per head: sv[g][i][d] = sum_{j>=i} vp[g][j][d], sv[g][L]=0
// ---------------------------------------------------------------------------
__global__ void sfx1(const float* __restrict__ vp, float* __restrict__ sv,
                     float* __restrict__ csum)
{
    int g = blockIdx.x;
    int c = blockIdx.y;
    int d = threadIdx.x;
    const float* v = vp + (size_t)g * L_SEQ * HD;
    float* s = sv + (size_t)g * (L_SEQ + 1) * HD;
    float a = 0.f;
    #pragma unroll 8
    for (int j = (c + 1) * 256 - 1; j >= c * 256; j--) {
        a += v[j * HD + d];
        s[j * HD + d] = a;
    }
    csum[(g * 8 + c) * HD + d] = a;
}

__global__ void sfx2(float* __restrict__ sv, const float* __restrict__ csum)
{
    int g = blockIdx.x;
    int c = blockIdx.y;
    int d = threadIdx.x;
    float* s = sv + (size_t)g * (L_SEQ + 1) * HD;
    if (c == 7) {
        s[L_SEQ * HD + d] = 0.f;
        return;
    }
    float off = 0.f;
    for (int c2 = c + 1; c2 < 8; c2++) off += csum[(g * 8 + c2) * HD + d];
    #pragma unroll 8
    for (int j = c * 256; j < (c + 1) * 256; j++)
        s[j * HD + d] += off;
}

// ---------------------------------------------------------------------------
// Attention over reinterpreted heads [NG, L, HD].
// Causal-only compute + online softmax; zero-block above the diagonal folded
// analytically via suffix sums of V.
// ---------------------------------------------------------------------------
__global__ __launch_bounds__(256) void attn_kernel(
    const float* __restrict__ qp, const float* __restrict__ kp,
    const float* __restrict__ vp, const float* __restrict__ sv,
    float* __restrict__ ctx)
{
    const int g  = blockIdx.y;
    const int qi = blockIdx.x;
    const int i0 = qi * 64;
    const float* Qh = qp + (size_t)g * L_SEQ * HD;
    const float* Kh = kp + (size_t)g * L_SEQ * HD;
    const float* Vh = vp + (size_t)g * L_SEQ * HD;

    __shared__ float Qs[64][68];
    __shared__ float Ks[32][68];
    __shared__ float Vs[32][68];
    __shared__ float Ss[64][36];
    __shared__ float row_m[64], row_l[64], row_a[64], row_b[64];

    const int t  = threadIdx.x;
    const int tx = t & 15, ty = t >> 4;

    #pragma unroll
    for (int rep = 0; rep < 4; rep++) {
        int idx = t + rep * 256;
        int r = idx >> 4, c4 = (idx & 15) * 4;
        *(float4*)&Qs[r][c4] = *(const float4*)&Qh[(size_t)(i0 + r) * HD + c4];
    }
    if (t < 64) { row_m[t] = -1e30f; row_l[t] = 0.f; }
    float acc[4][4] = {};
    __syncthreads();

    const int num_kb = qi * 2 + 2;
    for (int kb = 0; kb < num_kb; kb++) {
        const int j0 = kb * 32;
        #pragma unroll
        for (int rep = 0; rep < 2; rep++) {
            int idx = t + rep * 256;
            int r = idx >> 4, c4 = (idx & 15) * 4;
            *(float4*)&Ks[r][c4] = *(const float4*)&Kh[(size_t)(j0 + r) * HD + c4];
            *(float4*)&Vs[r][c4] = *(const float4*)&Vh[(size_t)(j0 + r) * HD + c4];
        }
        __syncthreads();

        // S tile
        float s[4][2] = {};
        #pragma unroll
        for (int k4 = 0; k4 < 16; k4++) {
            float4 k0v = *(const float4*)&Ks[tx*2+0][k4*4];
            float4 k1v = *(const float4*)&Ks[tx*2+1][k4*4];
            #pragma unroll
            for (int i = 0; i < 4; i++) {
                float4 qv = *(const float4*)&Qs[ty*4+i][k4*4];
                s[i][0] += qv.x*k0v.x + qv.y*k0v.y + qv.z*k0v.z + qv.w*k0v.w;
                s[i][1] += qv.x*k1v.x + qv.y*k1v.y + qv.z*k1v.z + qv.w*k1v.w;
            }
        }
        #pragma unroll
        for (int i = 0; i < 4; i++) {
            int gi = i0 + ty*4 + i;
            #pragma unroll
            for (int c = 0; c < 2; c++) {
                int gj = j0 + tx*2 + c;
                Ss[ty*4+i][tx*2+c] = (gj > gi) ? -1e30f : s[i][c] * 0.125f;
            }
        }
        __syncthreads();

        // parallel online softmax: 4 threads per row, 8 cols each
        {
            int row = t >> 2, q = t & 3;
            float m_old = row_m[row];
            float mloc = -1e30f;
            #pragma unroll
            for (int c = q*8; c < q*8 + 8; c++) mloc = fmaxf(mloc, Ss[row][c]);
            mloc = fmaxf(mloc, __shfl_xor_sync(0xffffffffu, mloc, 1));
            mloc = fmaxf(mloc, __shfl_xor_sync(0xffffffffu, mloc, 2));
            float m = fmaxf(m_old, mloc);
            float lsum = 0.f;
            #pragma unroll
            for (int c = q*8; c < q*8 + 8; c++) {
                float p = __expf(Ss[row][c] - m);
                Ss[row][c] = p;
                lsum += p;
            }
            lsum += __shfl_xor_sync(0xffffffffu, lsum, 1);
            lsum += __shfl_xor_sync(0xffffffffu, lsum, 2);
            if (q == 0) {
                float scale = __expf(m_old - m);
                row_m[row] = m;
                row_l[row] = row_l[row] * scale + lsum;
                row_a[row] = scale;
            }
        }
        __syncthreads();

        // rescale accumulator, then acc += P(64x32) @ V(32x64)
        float rs[4];
        #pragma unroll
        for (int i = 0; i < 4; i++) rs[i] = row_a[ty*4+i];
        #pragma unroll
        for (int i = 0; i < 4; i++)
            #pragma unroll
            for (int j = 0; j < 4; j++) acc[i][j] *= rs[i];

        #pragma unroll
        for (int kk4 = 0; kk4 < 8; kk4++) {
            float pr[4][4];
            #pragma unroll
            for (int i = 0; i < 4; i++) {
                float4 p4 = *(const float4*)&Ss[ty*4+i][kk4*4];
                pr[i][0]=p4.x; pr[i][1]=p4.y; pr[i][2]=p4.z; pr[i][3]=p4.w;
            }
            #pragma unroll
            for (int c = 0; c < 4; c++) {
                float4 vv = *(const float4*)&Vs[kk4*4+c][tx*4];
                float vm[4] = {vv.x, vv.y, vv.z, vv.w};
                #pragma unroll
                for (int i = 0; i < 4; i++)
                    #pragma unroll
                    for (int j = 0; j < 4; j++)
                        acc[i][j] += pr[i][c] * vm[j];
            }
        }
        __syncthreads();
    }

    // fold in the zero-block
    if (t < 64) {
        float m = row_m[t], l = row_l[t];
        float mf = fmaxf(m, 0.f);
        int ig = i0 + t;
        float cnt = (float)(L_SEQ - 1 - ig);
        float ez = __expf(-mf);
        float sc = __expf(m - mf);
        float lf = l * sc + cnt * ez;
        row_a[t] = sc;
        row_b[t] = ez;
        row_l[t] = 1.f / lf;
    }
    __syncthreads();

    const float* svg = sv + (size_t)g * (L_SEQ + 1) * HD;
    float* ctxg = ctx + (size_t)g * L_SEQ * HD;
    #pragma unroll
    for (int i = 0; i < 4; i++) {
        int r = ty*4 + i;
        int ig = i0 + r;
        float scf = row_a[r], ez = row_b[r], inv = row_l[r];
        float4 svv = *(const float4*)&svg[(size_t)(ig + 1) * HD + tx*4];
        float4 o;
        o.x = (acc[i][0]*scf + ez*svv.x) * inv;
        o.y = (acc[i][1]*scf + ez*svv.y) * inv;
        o.z = (acc[i][2]*scf + ez*svv.z) * inv;
        o.w = (acc[i][3]*scf + ez*svv.w) * inv;
        *(float4*)&ctxg[(size_t)ig * HD + tx*4] = o;
    }
}

// ---------------------------------------------------------------------------
extern "C" void kernel_launch(void* const* d_in, const int* in_sizes, int n_in,
                              void* d_out, int out_size)
{
    const float* q     = (const float*)d_in[0];
    const float* k     = (const float*)d_in[1];
    const float* v     = (const float*)d_in[2];
    // d_in[3] = attn_mask (causal by construction; handled analytically)
    const float* wq_w  = (const float*)d_in[4];
    const float* wq_b  = (const float*)d_in[5];
    const float* out_w = (const float*)d_in[6];
    const float* out_b = (const float*)d_in[7];
    float* out = (float*)d_out;

    float *qp, *kp, *vp, *ctx, *sv, *csum;
    cudaGetSymbolAddress((void**)&qp,   g_qp);
    cudaGetSymbolAddress((void**)&kp,   g_kp);
    cudaGetSymbolAddress((void**)&vp,   g_vp);
    cudaGetSymbolAddress((void**)&ctx,  g_ctx);
    cudaGetSymbolAddress((void**)&sv,   g_sv);
    cudaGetSymbolAddress((void**)&csum, g_csum);

    dim3 gg(MTOT / 128, DM / 128);
    gemm_tf32_bias<<<gg, 256>>>(q, wq_w, wq_b, qp, MTOT, DM, DM);
    gemm_tf32_bias<<<gg, 256>>>(k, wq_w, wq_b, kp, MTOT, DM, DM);
    gemm_tf32_bias<<<gg, 256>>>(v, wq_w, wq_b, vp, MTOT, DM, DM);
    sfx1<<<dim3(NG, 8), HD>>>(vp, sv, csum);
    sfx2<<<dim3(NG, 8), HD>>>(sv, csum);
    attn_kernel<<<dim3(L_SEQ / 64, NG), 256>>>(qp, kp, vp, sv, ctx);
    gemm_tf32_bias<<<gg, 256>>>(ctx, out_w, out_b, out, MTOT, DM, DM);
}

// round 7
// speedup vs baseline: 1.3418x; 1.2906x over previous
#include <cuda_runtime.h>
#include <cuda_bf16.h>
#include <cstdint>

#define L_SEQ 2048
#define DM 1024
#define HD 64
#define NG 32            // b * n_head after buggy reshape = 2*16
#define MTOT 4096        // B * L

// ---------------------------------------------------------------------------
// Scratch (static device globals -- no allocation allowed)
// ---------------------------------------------------------------------------
__device__ float g_qp[MTOT * DM];
__device__ float g_kp[MTOT * DM];
__device__ float g_vp[MTOT * DM];
__device__ float g_ctx[MTOT * DM];
__device__ float g_sv[NG * (L_SEQ + 1) * HD];   // suffix sums of V per head
__device__ float g_csum[NG * 8 * HD];
// bf16 hi/lo split buffers
__device__ __nv_bfloat16 g_ah[MTOT * DM];
__device__ __nv_bfloat16 g_al[MTOT * DM];
__device__ __nv_bfloat16 g_wh[DM * DM];
__device__ __nv_bfloat16 g_wl[DM * DM];
__device__ __nv_bfloat16 g_oh[DM * DM];
__device__ __nv_bfloat16 g_ol[DM * DM];

// ---------------------------------------------------------------------------
// bf16 m16n8k16 MMA (f32 accumulate) -- supported on compute_100 plain target
// ---------------------------------------------------------------------------
#define MMA_BF16(d, a, b) asm volatile( \
  "mma.sync.aligned.m16n8k16.row.col.f32.bf16.bf16.f32 " \
  "{%0,%1,%2,%3}, {%4,%5,%6,%7}, {%8,%9}, {%0,%1,%2,%3};\n" \
  : "+f"((d)[0]), "+f"((d)[1]), "+f"((d)[2]), "+f"((d)[3]) \
  : "r"((a)[0]), "r"((a)[1]), "r"((a)[2]), "r"((a)[3]), \
    "r"((b)[0]), "r"((b)[1]))

// ---------------------------------------------------------------------------
// fp32 -> bf16 hi/lo split (elementwise, float4 per thread)
// ---------------------------------------------------------------------------
__global__ void split_bf16(const float4* __restrict__ x,
                           uint2* __restrict__ hi, uint2* __restrict__ lo, int n4)
{
    int i = blockIdx.x * blockDim.x + threadIdx.x;
    if (i >= n4) return;
    float4 v = x[i];
    float vv[4] = {v.x, v.y, v.z, v.w};
    unsigned short hs[4], ls[4];
    #pragma unroll
    for (int j = 0; j < 4; j++) {
        __nv_bfloat16 h = __float2bfloat16(vv[j]);
        __nv_bfloat16 l = __float2bfloat16(vv[j] - __bfloat162float(h));
        hs[j] = __bfloat16_as_ushort(h);
        ls[j] = __bfloat16_as_ushort(l);
    }
    hi[i] = make_uint2((uint32_t)hs[0] | ((uint32_t)hs[1] << 16),
                       (uint32_t)hs[2] | ((uint32_t)hs[3] << 16));
    lo[i] = make_uint2((uint32_t)ls[0] | ((uint32_t)ls[1] << 16),
                       (uint32_t)ls[2] | ((uint32_t)ls[3] << 16));
}

// ---------------------------------------------------------------------------
// NT GEMM via mma.sync bf16 split: C = Ah*Bh^T + Ah*Bl^T + Al*Bh^T + bias
// CTA tile 128x128, BK=32 bf16, 8 warps (2x4), warp tile 64x32.
// Fragment layout (m16n8k16, row.col):
//   a0=(g,2tg) a1=(g+8,2tg) a2=(g,2tg+8) a3=(g+8,2tg+8)   [u32 = 2 bf16 in k]
//   b0=(n=g, k=2tg) b1=(n=g, k=2tg+8)
//   c0=(g,2tg) c1=(g,2tg+1) c2=(g+8,2tg) c3=(g+8,2tg+1)
// Both A and B are k-major in gmem/smem, so all fragment loads are plain u32.
// ---------------------------------------------------------------------------
#define BK 32
#define SSTR 40    // smem row stride in bf16 (pad 8 -> conflict-free)

__global__ __launch_bounds__(256) void gemm_bf16_mma(
    const __nv_bfloat16* __restrict__ Ah, const __nv_bfloat16* __restrict__ Al,
    const __nv_bfloat16* __restrict__ Bh, const __nv_bfloat16* __restrict__ Bl,
    const float* __restrict__ bias, float* __restrict__ C,
    int M, int N, int K)
{
    __shared__ __nv_bfloat16 sAh[128][SSTR], sAl[128][SSTR];
    __shared__ __nv_bfloat16 sBh[128][SSTR], sBl[128][SSTR];

    const int t    = threadIdx.x;
    const int lane = t & 31;
    const int warp = t >> 5;
    const int g    = lane >> 2;       // 0..7
    const int tg   = lane & 3;        // 0..3
    const int wm   = warp >> 2;       // 0..1
    const int wn   = warp & 3;        // 0..3
    const int bm   = blockIdx.x * 128, bn = blockIdx.y * 128;

    const int lr = t >> 1;            // 0..127
    const int lc = (t & 1) * 16;      // 0 or 16 (bf16 elems)

    float acc[4][4][4] = {};          // [mtile][ntile][4]

    const __nv_bfloat16* pAh = Ah + (size_t)(bm + lr) * K + lc;
    const __nv_bfloat16* pAl = Al + (size_t)(bm + lr) * K + lc;
    const __nv_bfloat16* pBh = Bh + (size_t)(bn + lr) * K + lc;
    const __nv_bfloat16* pBl = Bl + (size_t)(bn + lr) * K + lc;

    for (int kc = 0; kc < K; kc += BK) {
        // global -> smem (2 x uint4 = 16 bf16 per tile per thread)
        *(uint4*)&sAh[lr][lc]     = *(const uint4*)(pAh + kc);
        *(uint4*)&sAh[lr][lc + 8] = *(const uint4*)(pAh + kc + 8);
        *(uint4*)&sAl[lr][lc]     = *(const uint4*)(pAl + kc);
        *(uint4*)&sAl[lr][lc + 8] = *(const uint4*)(pAl + kc + 8);
        *(uint4*)&sBh[lr][lc]     = *(const uint4*)(pBh + kc);
        *(uint4*)&sBh[lr][lc + 8] = *(const uint4*)(pBh + kc + 8);
        *(uint4*)&sBl[lr][lc]     = *(const uint4*)(pBl + kc);
        *(uint4*)&sBl[lr][lc + 8] = *(const uint4*)(pBl + kc + 8);
        __syncthreads();

        #pragma unroll
        for (int ks = 0; ks < 2; ks++) {
            const int kof = ks * 16 + tg * 2;
            uint32_t ah[4][4], al[4][4], bh[4][2], bl[4][2];
            #pragma unroll
            for (int mt = 0; mt < 4; mt++) {
                int row = wm * 64 + mt * 16 + g;
                ah[mt][0] = *(const uint32_t*)&sAh[row    ][kof];
                ah[mt][1] = *(const uint32_t*)&sAh[row + 8][kof];
                ah[mt][2] = *(const uint32_t*)&sAh[row    ][kof + 8];
                ah[mt][3] = *(const uint32_t*)&sAh[row + 8][kof + 8];
                al[mt][0] = *(const uint32_t*)&sAl[row    ][kof];
                al[mt][1] = *(const uint32_t*)&sAl[row + 8][kof];
                al[mt][2] = *(const uint32_t*)&sAl[row    ][kof + 8];
                al[mt][3] = *(const uint32_t*)&sAl[row + 8][kof + 8];
            }
            #pragma unroll
            for (int nt = 0; nt < 4; nt++) {
                int col = wn * 32 + nt * 8 + g;
                bh[nt][0] = *(const uint32_t*)&sBh[col][kof];
                bh[nt][1] = *(const uint32_t*)&sBh[col][kof + 8];
                bl[nt][0] = *(const uint32_t*)&sBl[col][kof];
                bl[nt][1] = *(const uint32_t*)&sBl[col][kof + 8];
            }
            #pragma unroll
            for (int mt = 0; mt < 4; mt++)
                #pragma unroll
                for (int nt = 0; nt < 4; nt++) {
                    MMA_BF16(acc[mt][nt], ah[mt], bh[nt]);
                    MMA_BF16(acc[mt][nt], ah[mt], bl[nt]);
                    MMA_BF16(acc[mt][nt], al[mt], bh[nt]);
                }
        }
        __syncthreads();
    }

    // epilogue with bias
    #pragma unroll
    for (int mt = 0; mt < 4; mt++) {
        int row = bm + wm * 64 + mt * 16 + g;
        #pragma unroll
        for (int nt = 0; nt < 4; nt++) {
            int col = bn + wn * 32 + nt * 8 + tg * 2;
            float2 b2 = *(const float2*)&bias[col];
            float2 o0 = {acc[mt][nt][0] + b2.x, acc[mt][nt][1] + b2.y};
            float2 o1 = {acc[mt][nt][2] + b2.x, acc[mt][nt][3] + b2.y};
            *(float2*)&C[(size_t)row * N + col]       = o0;
            *(float2*)&C[(size_t)(row + 8) * N + col] = o1;
        }
    }
}

// ---------------------------------------------------------------------------
// Suffix sums of V per head: sv[g][i][d] = sum_{j>=i} vp[g][j][d], sv[g][L]=0
// ---------------------------------------------------------------------------
__global__ void sfx1(const float* __restrict__ vp, float* __restrict__ sv,
                     float* __restrict__ csum)
{
    int g = blockIdx.x;
    int c = blockIdx.y;
    int d = threadIdx.x;
    const float* v = vp + (size_t)g * L_SEQ * HD;
    float* s = sv + (size_t)g * (L_SEQ + 1) * HD;
    float a = 0.f;
    #pragma unroll 8
    for (int j = (c + 1) * 256 - 1; j >= c * 256; j--) {
        a += v[j * HD + d];
        s[j * HD + d] = a;
    }
    csum[(g * 8 + c) * HD + d] = a;
}

__global__ void sfx2(float* __restrict__ sv, const float* __restrict__ csum)
{
    int g = blockIdx.x;
    int c = blockIdx.y;
    int d = threadIdx.x;
    float* s = sv + (size_t)g * (L_SEQ + 1) * HD;
    if (c == 7) {
        s[L_SEQ * HD + d] = 0.f;
        return;
    }
    float off = 0.f;
    for (int c2 = c + 1; c2 < 8; c2++) off += csum[(g * 8 + c2) * HD + d];
    #pragma unroll 8
    for (int j = c * 256; j < (c + 1) * 256; j++)
        s[j * HD + d] += off;
}

// ---------------------------------------------------------------------------
// Attention over reinterpreted heads [NG, L, HD] (known-good from R2/R3).
// Causal-only compute + online softmax; zero-block above the diagonal folded
// analytically via suffix sums of V.
// ---------------------------------------------------------------------------
__global__ __launch_bounds__(256) void attn_kernel(
    const float* __restrict__ qp, const float* __restrict__ kp,
    const float* __restrict__ vp, const float* __restrict__ sv,
    float* __restrict__ ctx)
{
    const int g  = blockIdx.y;
    const int qi = blockIdx.x;
    const int i0 = qi * 64;
    const float* Qh = qp + (size_t)g * L_SEQ * HD;
    const float* Kh = kp + (size_t)g * L_SEQ * HD;
    const float* Vh = vp + (size_t)g * L_SEQ * HD;

    __shared__ float Qs[64][68];
    __shared__ float Ks[32][68];
    __shared__ float Vs[32][68];
    __shared__ float Ss[64][36];
    __shared__ float row_m[64], row_l[64], row_a[64], row_b[64];

    const int t  = threadIdx.x;
    const int tx = t & 15, ty = t >> 4;

    #pragma unroll
    for (int rep = 0; rep < 4; rep++) {
        int idx = t + rep * 256;
        int r = idx >> 4, c4 = (idx & 15) * 4;
        *(float4*)&Qs[r][c4] = *(const float4*)&Qh[(size_t)(i0 + r) * HD + c4];
    }
    if (t < 64) { row_m[t] = -1e30f; row_l[t] = 0.f; }
    float acc[4][4] = {};
    __syncthreads();

    const int num_kb = qi * 2 + 2;
    for (int kb = 0; kb < num_kb; kb++) {
        const int j0 = kb * 32;
        #pragma unroll
        for (int rep = 0; rep < 2; rep++) {
            int idx = t + rep * 256;
            int r = idx >> 4, c4 = (idx & 15) * 4;
            *(float4*)&Ks[r][c4] = *(const float4*)&Kh[(size_t)(j0 + r) * HD + c4];
            *(float4*)&Vs[r][c4] = *(const float4*)&Vh[(size_t)(j0 + r) * HD + c4];
        }
        __syncthreads();

        float s[4][2] = {};
        #pragma unroll
        for (int k4 = 0; k4 < 16; k4++) {
            float4 k0v = *(const float4*)&Ks[tx*2+0][k4*4];
            float4 k1v = *(const float4*)&Ks[tx*2+1][k4*4];
            #pragma unroll
            for (int i = 0; i < 4; i++) {
                float4 qv = *(const float4*)&Qs[ty*4+i][k4*4];
                s[i][0] += qv.x*k0v.x + qv.y*k0v.y + qv.z*k0v.z + qv.w*k0v.w;
                s[i][1] += qv.x*k1v.x + qv.y*k1v.y + qv.z*k1v.z + qv.w*k1v.w;
            }
        }
        #pragma unroll
        for (int i = 0; i < 4; i++) {
            int gi = i0 + ty*4 + i;
            #pragma unroll
            for (int c = 0; c < 2; c++) {
                int gj = j0 + tx*2 + c;
                Ss[ty*4+i][tx*2+c] = (gj > gi) ? -1e30f : s[i][c] * 0.125f;
            }
        }
        __syncthreads();

        {
            int row = t >> 2, q = t & 3;
            float m_old = row_m[row];
            float mloc = -1e30f;
            #pragma unroll
            for (int c = q*8; c < q*8 + 8; c++) mloc = fmaxf(mloc, Ss[row][c]);
            mloc = fmaxf(mloc, __shfl_xor_sync(0xffffffffu, mloc, 1));
            mloc = fmaxf(mloc, __shfl_xor_sync(0xffffffffu, mloc, 2));
            float m = fmaxf(m_old, mloc);
            float lsum = 0.f;
            #pragma unroll
            for (int c = q*8; c < q*8 + 8; c++) {
                float p = __expf(Ss[row][c] - m);
                Ss[row][c] = p;
                lsum += p;
            }
            lsum += __shfl_xor_sync(0xffffffffu, lsum, 1);
            lsum += __shfl_xor_sync(0xffffffffu, lsum, 2);
            if (q == 0) {
                float scale = __expf(m_old - m);
                row_m[row] = m;
                row_l[row] = row_l[row] * scale + lsum;
                row_a[row] = scale;
            }
        }
        __syncthreads();

        float rs[4];
        #pragma unroll
        for (int i = 0; i < 4; i++) rs[i] = row_a[ty*4+i];
        #pragma unroll
        for (int i = 0; i < 4; i++)
            #pragma unroll
            for (int j = 0; j < 4; j++) acc[i][j] *= rs[i];

        #pragma unroll
        for (int kk4 = 0; kk4 < 8; kk4++) {
            float pr[4][4];
            #pragma unroll
            for (int i = 0; i < 4; i++) {
                float4 p4 = *(const float4*)&Ss[ty*4+i][kk4*4];
                pr[i][0]=p4.x; pr[i][1]=p4.y; pr[i][2]=p4.z; pr[i][3]=p4.w;
            }
            #pragma unroll
            for (int c = 0; c < 4; c++) {
                float4 vv = *(const float4*)&Vs[kk4*4+c][tx*4];
                float vm[4] = {vv.x, vv.y, vv.z, vv.w};
                #pragma unroll
                for (int i = 0; i < 4; i++)
                    #pragma unroll
                    for (int j = 0; j < 4; j++)
                        acc[i][j] += pr[i][c] * vm[j];
            }
        }
        __syncthreads();
    }

    if (t < 64) {
        float m = row_m[t], l = row_l[t];
        float mf = fmaxf(m, 0.f);
        int ig = i0 + t;
        float cnt = (float)(L_SEQ - 1 - ig);
        float ez = __expf(-mf);
        float sc = __expf(m - mf);
        float lf = l * sc + cnt * ez;
        row_a[t] = sc;
        row_b[t] = ez;
        row_l[t] = 1.f / lf;
    }
    __syncthreads();

    const float* svg = sv + (size_t)g * (L_SEQ + 1) * HD;
    float* ctxg = ctx + (size_t)g * L_SEQ * HD;
    #pragma unroll
    for (int i = 0; i < 4; i++) {
        int r = ty*4 + i;
        int ig = i0 + r;
        float scf = row_a[r], ez = row_b[r], inv = row_l[r];
        float4 svv = *(const float4*)&svg[(size_t)(ig + 1) * HD + tx*4];
        float4 o;
        o.x = (acc[i][0]*scf + ez*svv.x) * inv;
        o.y = (acc[i][1]*scf + ez*svv.y) * inv;
        o.z = (acc[i][2]*scf + ez*svv.z) * inv;
        o.w = (acc[i][3]*scf + ez*svv.w) * inv;
        *(float4*)&ctxg[(size_t)ig * HD + tx*4] = o;
    }
}

// ---------------------------------------------------------------------------
extern "C" void kernel_launch(void* const* d_in, const int* in_sizes, int n_in,
                              void* d_out, int out_size)
{
    const float* q     = (const float*)d_in[0];
    const float* k     = (const float*)d_in[1];
    const float* v     = (const float*)d_in[2];
    // d_in[3] = attn_mask (causal by construction; handled analytically)
    const float* wq_w  = (const float*)d_in[4];
    const float* wq_b  = (const float*)d_in[5];
    const float* out_w = (const float*)d_in[6];
    const float* out_b = (const float*)d_in[7];
    float* out = (float*)d_out;

    float *qp, *kp, *vp, *ctx, *sv, *csum;
    __nv_bfloat16 *ah, *al, *wh, *wl, *oh, *ol;
    cudaGetSymbolAddress((void**)&qp,   g_qp);
    cudaGetSymbolAddress((void**)&kp,   g_kp);
    cudaGetSymbolAddress((void**)&vp,   g_vp);
    cudaGetSymbolAddress((void**)&ctx,  g_ctx);
    cudaGetSymbolAddress((void**)&sv,   g_sv);
    cudaGetSymbolAddress((void**)&csum, g_csum);
    cudaGetSymbolAddress((void**)&ah,   g_ah);
    cudaGetSymbolAddress((void**)&al,   g_al);
    cudaGetSymbolAddress((void**)&wh,   g_wh);
    cudaGetSymbolAddress((void**)&wl,   g_wl);
    cudaGetSymbolAddress((void**)&oh,   g_oh);
    cudaGetSymbolAddress((void**)&ol,   g_ol);

    const int NA4 = MTOT * DM / 4;   // big matrix float4 count
    const int NW4 = DM * DM / 4;     // weight float4 count
    dim3 gg(MTOT / 128, DM / 128);

    // weight splits
    split_bf16<<<(NW4 + 255) / 256, 256>>>((const float4*)wq_w,  (uint2*)wh, (uint2*)wl, NW4);
    split_bf16<<<(NW4 + 255) / 256, 256>>>((const float4*)out_w, (uint2*)oh, (uint2*)ol, NW4);

    // q/k/v projections (reuse ah/al buffers serially)
    split_bf16<<<(NA4 + 255) / 256, 256>>>((const float4*)q, (uint2*)ah, (uint2*)al, NA4);
    gemm_bf16_mma<<<gg, 256>>>(ah, al, wh, wl, wq_b, qp, MTOT, DM, DM);
    split_bf16<<<(NA4 + 255) / 256, 256>>>((const float4*)k, (uint2*)ah, (uint2*)al, NA4);
    gemm_bf16_mma<<<gg, 256>>>(ah, al, wh, wl, wq_b, kp, MTOT, DM, DM);
    split_bf16<<<(NA4 + 255) / 256, 256>>>((const float4*)v, (uint2*)ah, (uint2*)al, NA4);
    gemm_bf16_mma<<<gg, 256>>>(ah, al, wh, wl, wq_b, vp, MTOT, DM, DM);

    sfx1<<<dim3(NG, 8), HD>>>(vp, sv, csum);
    sfx2<<<dim3(NG, 8), HD>>>(sv, csum);
    attn_kernel<<<dim3(L_SEQ / 64, NG), 256>>>(qp, kp, vp, sv, ctx);

    // output projection
    split_bf16<<<(NA4 + 255) / 256, 256>>>((const float4*)ctx, (uint2*)ah, (uint2*)al, NA4);
    gemm_bf16_mma<<<gg, 256>>>(ah, al, oh, ol, out_b, out, MTOT, DM, DM);
}

// round 10
// speedup vs baseline: 2.0060x; 1.4950x over previous
#include <cuda_runtime.h>
#include <cuda_bf16.h>
#include <cstdint>

#define L_SEQ 2048
#define DM 1024
#define HD 64
#define NG 32            // b * n_head after buggy reshape = 2*16
#define MTOT 4096        // B * L

// ---------------------------------------------------------------------------
// Scratch (static device globals -- no allocation allowed)
// ---------------------------------------------------------------------------
__device__ float g_qp[MTOT * DM];
__device__ float g_kp[MTOT * DM];
__device__ float g_vp[MTOT * DM];
__device__ float g_sv[NG * (L_SEQ + 1) * HD];   // suffix sums of V per head
__device__ float g_csum[NG * 8 * HD];
// bf16 hi/lo split buffers
__device__ __nv_bfloat16 g_ah[MTOT * DM];
__device__ __nv_bfloat16 g_al[MTOT * DM];
__device__ __nv_bfloat16 g_wh[DM * DM];
__device__ __nv_bfloat16 g_wl[DM * DM];
__device__ __nv_bfloat16 g_oh[DM * DM];
__device__ __nv_bfloat16 g_ol[DM * DM];

// ---------------------------------------------------------------------------
// bf16 m16n8k16 MMA (f32 accumulate)
// ---------------------------------------------------------------------------
#define MMA_BF16(d, a, b) asm volatile( \
  "mma.sync.aligned.m16n8k16.row.col.f32.bf16.bf16.f32 " \
  "{%0,%1,%2,%3}, {%4,%5,%6,%7}, {%8,%9}, {%0,%1,%2,%3};\n" \
  : "+f"((d)[0]), "+f"((d)[1]), "+f"((d)[2]), "+f"((d)[3]) \
  : "r"((a)[0]), "r"((a)[1]), "r"((a)[2]), "r"((a)[3]), \
    "r"((b)[0]), "r"((b)[1]))

__device__ __forceinline__ void split2(float x, float y, uint32_t& hi, uint32_t& lo)
{
    __nv_bfloat16 hx = __float2bfloat16(x);
    __nv_bfloat16 hy = __float2bfloat16(y);
    __nv_bfloat16 lx = __float2bfloat16(x - __bfloat162float(hx));
    __nv_bfloat16 ly = __float2bfloat16(y - __bfloat162float(hy));
    hi = (uint32_t)__bfloat16_as_ushort(hx) | ((uint32_t)__bfloat16_as_ushort(hy) << 16);
    lo = (uint32_t)__bfloat16_as_ushort(lx) | ((uint32_t)__bfloat16_as_ushort(ly) << 16);
}

// ---------------------------------------------------------------------------
// fp32 -> bf16 hi/lo split (elementwise, float4 per thread)
// ---------------------------------------------------------------------------
__global__ void split_bf16(const float4* __restrict__ x,
                           uint2* __restrict__ hi, uint2* __restrict__ lo, int n4)
{
    int i = blockIdx.x * blockDim.x + threadIdx.x;
    if (i >= n4) return;
    float4 v = x[i];
    uint32_t h0, l0, h1, l1;
    split2(v.x, v.y, h0, l0);
    split2(v.z, v.w, h1, l1);
    hi[i] = make_uint2(h0, h1);
    lo[i] = make_uint2(l0, l1);
}

// ---------------------------------------------------------------------------
// NT GEMM via mma.sync bf16 split (validated R6/R7): C = AhBh+AhBl+AlBh + bias
// ---------------------------------------------------------------------------
#define BK 32
#define SSTR 40

__global__ __launch_bounds__(256) void gemm_bf16_mma(
    const __nv_bfloat16* __restrict__ Ah, const __nv_bfloat16* __restrict__ Al,
    const __nv_bfloat16* __restrict__ Bh, const __nv_bfloat16* __restrict__ Bl,
    const float* __restrict__ bias, float* __restrict__ C,
    int M, int N, int K)
{
    __shared__ __nv_bfloat16 sAh[128][SSTR], sAl[128][SSTR];
    __shared__ __nv_bfloat16 sBh[128][SSTR], sBl[128][SSTR];

    const int t    = threadIdx.x;
    const int lane = t & 31;
    const int warp = t >> 5;
    const int g    = lane >> 2;
    const int tg   = lane & 3;
    const int wm   = warp >> 2;
    const int wn   = warp & 3;
    const int bm   = blockIdx.x * 128, bn = blockIdx.y * 128;

    const int lr = t >> 1;
    const int lc = (t & 1) * 16;

    float acc[4][4][4] = {};

    const __nv_bfloat16* pAh = Ah + (size_t)(bm + lr) * K + lc;
    const __nv_bfloat16* pAl = Al + (size_t)(bm + lr) * K + lc;
    const __nv_bfloat16* pBh = Bh + (size_t)(bn + lr) * K + lc;
    const __nv_bfloat16* pBl = Bl + (size_t)(bn + lr) * K + lc;

    for (int kc = 0; kc < K; kc += BK) {
        *(uint4*)&sAh[lr][lc]     = *(const uint4*)(pAh + kc);
        *(uint4*)&sAh[lr][lc + 8] = *(const uint4*)(pAh + kc + 8);
        *(uint4*)&sAl[lr][lc]     = *(const uint4*)(pAl + kc);
        *(uint4*)&sAl[lr][lc + 8] = *(const uint4*)(pAl + kc + 8);
        *(uint4*)&sBh[lr][lc]     = *(const uint4*)(pBh + kc);
        *(uint4*)&sBh[lr][lc + 8] = *(const uint4*)(pBh + kc + 8);
        *(uint4*)&sBl[lr][lc]     = *(const uint4*)(pBl + kc);
        *(uint4*)&sBl[lr][lc + 8] = *(const uint4*)(pBl + kc + 8);
        __syncthreads();

        #pragma unroll
        for (int ks = 0; ks < 2; ks++) {
            const int kof = ks * 16 + tg * 2;
            uint32_t ah[4][4], al[4][4], bh[4][2], bl[4][2];
            #pragma unroll
            for (int mt = 0; mt < 4; mt++) {
                int row = wm * 64 + mt * 16 + g;
                ah[mt][0] = *(const uint32_t*)&sAh[row    ][kof];
                ah[mt][1] = *(const uint32_t*)&sAh[row + 8][kof];
                ah[mt][2] = *(const uint32_t*)&sAh[row    ][kof + 8];
                ah[mt][3] = *(const uint32_t*)&sAh[row + 8][kof + 8];
                al[mt][0] = *(const uint32_t*)&sAl[row    ][kof];
                al[mt][1] = *(const uint32_t*)&sAl[row + 8][kof];
                al[mt][2] = *(const uint32_t*)&sAl[row    ][kof + 8];
                al[mt][3] = *(const uint32_t*)&sAl[row + 8][kof + 8];
            }
            #pragma unroll
            for (int nt = 0; nt < 4; nt++) {
                int col = wn * 32 + nt * 8 + g;
                bh[nt][0] = *(const uint32_t*)&sBh[col][kof];
                bh[nt][1] = *(const uint32_t*)&sBh[col][kof + 8];
                bl[nt][0] = *(const uint32_t*)&sBl[col][kof];
                bl[nt][1] = *(const uint32_t*)&sBl[col][kof + 8];
            }
            #pragma unroll
            for (int mt = 0; mt < 4; mt++)
                #pragma unroll
                for (int nt = 0; nt < 4; nt++) {
                    MMA_BF16(acc[mt][nt], ah[mt], bh[nt]);
                    MMA_BF16(acc[mt][nt], ah[mt], bl[nt]);
                    MMA_BF16(acc[mt][nt], al[mt], bh[nt]);
                }
        }
        __syncthreads();
    }

    #pragma unroll
    for (int mt = 0; mt < 4; mt++) {
        int row = bm + wm * 64 + mt * 16 + g;
        #pragma unroll
        for (int nt = 0; nt < 4; nt++) {
            int col = bn + wn * 32 + nt * 8 + tg * 2;
            float2 b2 = *(const float2*)&bias[col];
            float2 o0 = {acc[mt][nt][0] + b2.x, acc[mt][nt][1] + b2.y};
            float2 o1 = {acc[mt][nt][2] + b2.x, acc[mt][nt][3] + b2.y};
            *(float2*)&C[(size_t)row * N + col]       = o0;
            *(float2*)&C[(size_t)(row + 8) * N + col] = o1;
        }
    }
}

// ---------------------------------------------------------------------------
// Suffix sums of V per head
// ---------------------------------------------------------------------------
__global__ void sfx1(const float* __restrict__ vp, float* __restrict__ sv,
                     float* __restrict__ csum)
{
    int g = blockIdx.x, c = blockIdx.y, d = threadIdx.x;
    const float* v = vp + (size_t)g * L_SEQ * HD;
    float* s = sv + (size_t)g * (L_SEQ + 1) * HD;
    float a = 0.f;
    #pragma unroll 8
    for (int j = (c + 1) * 256 - 1; j >= c * 256; j--) {
        a += v[j * HD + d];
        s[j * HD + d] = a;
    }
    csum[(g * 8 + c) * HD + d] = a;
}

__global__ void sfx2(float* __restrict__ sv, const float* __restrict__ csum)
{
    int g = blockIdx.x, c = blockIdx.y, d = threadIdx.x;
    float* s = sv + (size_t)g * (L_SEQ + 1) * HD;
    if (c == 7) { s[L_SEQ * HD + d] = 0.f; return; }
    float off = 0.f;
    for (int c2 = c + 1; c2 < 8; c2++) off += csum[(g * 8 + c2) * HD + d];
    #pragma unroll 8
    for (int j = c * 256; j < (c + 1) * 256; j++)
        s[j * HD + d] += off;
}

// ---------------------------------------------------------------------------
// Tensor-core flash attention over reinterpreted heads [NG, L, HD].
// 128 threads (4 warps), 64 q-rows/block, 64-key tiles. Q fragments held in
// registers (loaded once from gmem); K/V split into smem (36.8KB static).
// bf16-split MMAs for S=QK^T and O+=PV; quad-shuffle online softmax; suffix-
// sum zero-block fold; ctx written directly as bf16 hi/lo.
// ---------------------------------------------------------------------------
#define ASTR 72

__global__ __launch_bounds__(128) void attn_mma(
    const float* __restrict__ qp, const float* __restrict__ kp,
    const float* __restrict__ vp, const float* __restrict__ sv,
    __nv_bfloat16* __restrict__ ch, __nv_bfloat16* __restrict__ cl)
{
    const int g  = blockIdx.y;
    const int qi = 31 - blockIdx.x;      // big tiles launch first
    const int i0 = qi * 64;
    const float* Qg = qp + (size_t)g * L_SEQ * HD;
    const float* Kg = kp + (size_t)g * L_SEQ * HD;
    const float* Vg = vp + (size_t)g * L_SEQ * HD;
    const float* svg = sv + (size_t)g * (L_SEQ + 1) * HD;

    __shared__ __nv_bfloat16 Kh[64][ASTR], Kl[64][ASTR];
    __shared__ __nv_bfloat16 Vh[64][ASTR], Vl[64][ASTR];   // transposed [d][key]

    const int t    = threadIdx.x;
    const int lane = t & 31;
    const int warp = t >> 5;
    const int gq   = lane >> 2;      // 0..7
    const int tg   = lane & 3;       // 0..3

    const int r0g = i0 + warp * 16 + gq;     // global q rows this thread owns
    const int r1g = r0g + 8;

    // ---- Q fragments -> registers (reused for every key tile) ----
    uint32_t qah[4][4], qal[4][4];
    #pragma unroll
    for (int kc = 0; kc < 4; kc++) {
        const int kof = kc * 16 + tg * 2;
        float2 q00 = *(const float2*)&Qg[(size_t)r0g * HD + kof];
        float2 q10 = *(const float2*)&Qg[(size_t)r1g * HD + kof];
        float2 q01 = *(const float2*)&Qg[(size_t)r0g * HD + kof + 8];
        float2 q11 = *(const float2*)&Qg[(size_t)r1g * HD + kof + 8];
        split2(q00.x, q00.y, qah[kc][0], qal[kc][0]);
        split2(q10.x, q10.y, qah[kc][1], qal[kc][1]);
        split2(q01.x, q01.y, qah[kc][2], qal[kc][2]);
        split2(q11.x, q11.y, qah[kc][3], qal[kc][3]);
    }

    float oacc[8][4] = {};
    float m0 = -1e30f, m1 = -1e30f, l0s = 0.f, l1s = 0.f;

    for (int kb = 0; kb <= qi; kb++) {
        const int j0 = kb * 64;
        // load + split K (row-major) and V (transposed)
        #pragma unroll
        for (int rep = 0; rep < 8; rep++) {
            int idx = t + rep * 128;
            int r = idx >> 4, d4 = (idx & 15) * 4;
            float4 kv = *(const float4*)&Kg[(size_t)(j0 + r) * HD + d4];
            uint32_t h0, l0, h1, l1;
            split2(kv.x, kv.y, h0, l0);
            split2(kv.z, kv.w, h1, l1);
            *(uint32_t*)&Kh[r][d4]     = h0;  *(uint32_t*)&Kh[r][d4 + 2] = h1;
            *(uint32_t*)&Kl[r][d4]     = l0;  *(uint32_t*)&Kl[r][d4 + 2] = l1;
            float4 vv = *(const float4*)&Vg[(size_t)(j0 + r) * HD + d4];
            float va[4] = {vv.x, vv.y, vv.z, vv.w};
            #pragma unroll
            for (int j = 0; j < 4; j++) {
                __nv_bfloat16 h = __float2bfloat16(va[j]);
                __nv_bfloat16 l = __float2bfloat16(va[j] - __bfloat162float(h));
                Vh[d4 + j][r] = h;
                Vl[d4 + j][r] = l;
            }
        }
        __syncthreads();

        // ---- S = Q K^T ----
        float sacc[8][4] = {};
        #pragma unroll
        for (int kc = 0; kc < 4; kc++) {
            const int kof = kc * 16 + tg * 2;
            #pragma unroll
            for (int nt = 0; nt < 8; nt++) {
                uint32_t bh[2], bl[2];
                bh[0] = *(const uint32_t*)&Kh[nt * 8 + gq][kof];
                bh[1] = *(const uint32_t*)&Kh[nt * 8 + gq][kof + 8];
                bl[0] = *(const uint32_t*)&Kl[nt * 8 + gq][kof];
                bl[1] = *(const uint32_t*)&Kl[nt * 8 + gq][kof + 8];
                MMA_BF16(sacc[nt], qah[kc], bh);
                MMA_BF16(sacc[nt], qah[kc], bl);
                MMA_BF16(sacc[nt], qal[kc], bh);
            }
        }

        // ---- scale + causal mask ----
        #pragma unroll
        for (int nt = 0; nt < 8; nt++) {
            int c0 = j0 + nt * 8 + tg * 2, c1 = c0 + 1;
            sacc[nt][0] = (c0 > r0g) ? -1e30f : sacc[nt][0] * 0.125f;
            sacc[nt][1] = (c1 > r0g) ? -1e30f : sacc[nt][1] * 0.125f;
            sacc[nt][2] = (c0 > r1g) ? -1e30f : sacc[nt][2] * 0.125f;
            sacc[nt][3] = (c1 > r1g) ? -1e30f : sacc[nt][3] * 0.125f;
        }

        // ---- online softmax (quad reduce over tg lanes) ----
        float mx0 = -1e30f, mx1 = -1e30f;
        #pragma unroll
        for (int nt = 0; nt < 8; nt++) {
            mx0 = fmaxf(mx0, fmaxf(sacc[nt][0], sacc[nt][1]));
            mx1 = fmaxf(mx1, fmaxf(sacc[nt][2], sacc[nt][3]));
        }
        mx0 = fmaxf(mx0, __shfl_xor_sync(0xffffffffu, mx0, 1));
        mx0 = fmaxf(mx0, __shfl_xor_sync(0xffffffffu, mx0, 2));
        mx1 = fmaxf(mx1, __shfl_xor_sync(0xffffffffu, mx1, 1));
        mx1 = fmaxf(mx1, __shfl_xor_sync(0xffffffffu, mx1, 2));
        float mn0 = fmaxf(m0, mx0), mn1 = fmaxf(m1, mx1);
        float sc0 = __expf(m0 - mn0), sc1 = __expf(m1 - mn1);
        m0 = mn0; m1 = mn1;

        // P = exp(S - m), pack into bf16 hi/lo A-fragments, accumulate l
        uint32_t pah[4][4], pal[4][4];
        float ls0 = 0.f, ls1 = 0.f;
        #pragma unroll
        for (int c = 0; c < 4; c++) {
            float p00 = __expf(sacc[2*c  ][0] - mn0), p01 = __expf(sacc[2*c  ][1] - mn0);
            float p10 = __expf(sacc[2*c  ][2] - mn1), p11 = __expf(sacc[2*c  ][3] - mn1);
            float p20 = __expf(sacc[2*c+1][0] - mn0), p21 = __expf(sacc[2*c+1][1] - mn0);
            float p30 = __expf(sacc[2*c+1][2] - mn1), p31 = __expf(sacc[2*c+1][3] - mn1);
            ls0 += p00 + p01 + p20 + p21;
            ls1 += p10 + p11 + p30 + p31;
            split2(p00, p01, pah[c][0], pal[c][0]);
            split2(p10, p11, pah[c][1], pal[c][1]);
            split2(p20, p21, pah[c][2], pal[c][2]);
            split2(p30, p31, pah[c][3], pal[c][3]);
        }
        ls0 += __shfl_xor_sync(0xffffffffu, ls0, 1);
        ls0 += __shfl_xor_sync(0xffffffffu, ls0, 2);
        ls1 += __shfl_xor_sync(0xffffffffu, ls1, 1);
        ls1 += __shfl_xor_sync(0xffffffffu, ls1, 2);
        l0s = l0s * sc0 + ls0;
        l1s = l1s * sc1 + ls1;

        // rescale O
        #pragma unroll
        for (int dn = 0; dn < 8; dn++) {
            oacc[dn][0] *= sc0; oacc[dn][1] *= sc0;
            oacc[dn][2] *= sc1; oacc[dn][3] *= sc1;
        }

        // ---- O += P V ----
        #pragma unroll
        for (int c = 0; c < 4; c++) {
            const int kof = c * 16 + tg * 2;
            #pragma unroll
            for (int dn = 0; dn < 8; dn++) {
                uint32_t vh[2], vl[2];
                vh[0] = *(const uint32_t*)&Vh[dn * 8 + gq][kof];
                vh[1] = *(const uint32_t*)&Vh[dn * 8 + gq][kof + 8];
                vl[0] = *(const uint32_t*)&Vl[dn * 8 + gq][kof];
                vl[1] = *(const uint32_t*)&Vl[dn * 8 + gq][kof + 8];
                MMA_BF16(oacc[dn], pah[c], vh);
                MMA_BF16(oacc[dn], pah[c], vl);
                MMA_BF16(oacc[dn], pal[c], vh);
            }
        }
        __syncthreads();
    }

    // ---- fold zero-block (zeros above diagonal participate in softmax) ----
    float mf0 = fmaxf(m0, 0.f), mf1 = fmaxf(m1, 0.f);
    float ez0 = __expf(-mf0), ez1 = __expf(-mf1);
    float fc0 = __expf(m0 - mf0), fc1 = __expf(m1 - mf1);
    float inv0 = 1.f / (l0s * fc0 + (float)(L_SEQ - 1 - r0g) * ez0);
    float inv1 = 1.f / (l1s * fc1 + (float)(L_SEQ - 1 - r1g) * ez1);

    const size_t base = (size_t)g * L_SEQ * HD;
    #pragma unroll
    for (int dn = 0; dn < 8; dn++) {
        int d = dn * 8 + tg * 2;
        float2 s0 = *(const float2*)&svg[(size_t)(r0g + 1) * HD + d];
        float2 s1 = *(const float2*)&svg[(size_t)(r1g + 1) * HD + d];
        float o00 = (oacc[dn][0] * fc0 + ez0 * s0.x) * inv0;
        float o01 = (oacc[dn][1] * fc0 + ez0 * s0.y) * inv0;
        float o10 = (oacc[dn][2] * fc1 + ez1 * s1.x) * inv1;
        float o11 = (oacc[dn][3] * fc1 + ez1 * s1.y) * inv1;
        uint32_t h, l;
        split2(o00, o01, h, l);
        *(uint32_t*)&ch[base + (size_t)r0g * HD + d] = h;
        *(uint32_t*)&cl[base + (size_t)r0g * HD + d] = l;
        split2(o10, o11, h, l);
        *(uint32_t*)&ch[base + (size_t)r1g * HD + d] = h;
        *(uint32_t*)&cl[base + (size_t)r1g * HD + d] = l;
    }
}

// ---------------------------------------------------------------------------
extern "C" void kernel_launch(void* const* d_in, const int* in_sizes, int n_in,
                              void* d_out, int out_size)
{
    const float* q     = (const float*)d_in[0];
    const float* k     = (const float*)d_in[1];
    const float* v     = (const float*)d_in[2];
    // d_in[3] = attn_mask (causal by construction; handled analytically)
    const float* wq_w  = (const float*)d_in[4];
    const float* wq_b  = (const float*)d_in[5];
    const float* out_w = (const float*)d_in[6];
    const float* out_b = (const float*)d_in[7];
    float* out = (float*)d_out;

    float *qp, *kp, *vp, *sv, *csum;
    __nv_bfloat16 *ah, *al, *wh, *wl, *oh, *ol;
    cudaGetSymbolAddress((void**)&qp,   g_qp);
    cudaGetSymbolAddress((void**)&kp,   g_kp);
    cudaGetSymbolAddress((void**)&vp,   g_vp);
    cudaGetSymbolAddress((void**)&sv,   g_sv);
    cudaGetSymbolAddress((void**)&csum, g_csum);
    cudaGetSymbolAddress((void**)&ah,   g_ah);
    cudaGetSymbolAddress((void**)&al,   g_al);
    cudaGetSymbolAddress((void**)&wh,   g_wh);
    cudaGetSymbolAddress((void**)&wl,   g_wl);
    cudaGetSymbolAddress((void**)&oh,   g_oh);
    cudaGetSymbolAddress((void**)&ol,   g_ol);

    const int NA4 = MTOT * DM / 4;
    const int NW4 = DM * DM / 4;
    dim3 gg(MTOT / 128, DM / 128);

    // weight splits
    split_bf16<<<(NW4 + 255) / 256, 256>>>((const float4*)wq_w,  (uint2*)wh, (uint2*)wl, NW4);
    split_bf16<<<(NW4 + 255) / 256, 256>>>((const float4*)out_w, (uint2*)oh, (uint2*)ol, NW4);

    // q/k/v projections (reuse ah/al buffers serially)
    split_bf16<<<(NA4 + 255) / 256, 256>>>((const float4*)q, (uint2*)ah, (uint2*)al, NA4);
    gemm_bf16_mma<<<gg, 256>>>(ah, al, wh, wl, wq_b, qp, MTOT, DM, DM);
    split_bf16<<<(NA4 + 255) / 256, 256>>>((const float4*)k, (uint2*)ah, (uint2*)al, NA4);
    gemm_bf16_mma<<<gg, 256>>>(ah, al, wh, wl, wq_b, kp, MTOT, DM, DM);
    split_bf16<<<(NA4 + 255) / 256, 256>>>((const float4*)v, (uint2*)ah, (uint2*)al, NA4);
    gemm_bf16_mma<<<gg, 256>>>(ah, al, wh, wl, wq_b, vp, MTOT, DM, DM);

    sfx1<<<dim3(NG, 8), HD>>>(vp, sv, csum);
    sfx2<<<dim3(NG, 8), HD>>>(sv, csum);

    // tensor-core attention; writes ctx directly as bf16 hi/lo into ah/al
    attn_mma<<<dim3(L_SEQ / 64, NG), 128>>>(qp, kp, vp, sv, ah, al);

    // output projection
    gemm_bf16_mma<<<gg, 256>>>(ah, al, oh, ol, out_b, out, MTOT, DM, DM);
}

// round 13
// speedup vs baseline: 2.1778x; 1.0856x over previous
#include <cuda_runtime.h>
#include <cuda_bf16.h>
#include <cstdint>

#define L_SEQ 2048
#define DM 1024
#define HD 64
#define NG 32            // b * n_head after buggy reshape = 2*16
#define MTOT 4096        // B * L

// ---------------------------------------------------------------------------
// Scratch (static device globals -- no allocation allowed)
// ---------------------------------------------------------------------------
__device__ float g_qkvp[3 * MTOT * DM];          // projected q|k|v (contiguous)
__device__ float g_sv[NG * (L_SEQ + 1) * HD];    // suffix sums of V per head
__device__ float g_csum[NG * 8 * HD];
// bf16 hi/lo split buffers (holds q|k|v splits, later reused for ctx)
__device__ __nv_bfloat16 g_ah[3 * MTOT * DM];
__device__ __nv_bfloat16 g_al[3 * MTOT * DM];
__device__ __nv_bfloat16 g_wh[DM * DM];
__device__ __nv_bfloat16 g_wl[DM * DM];
__device__ __nv_bfloat16 g_oh[DM * DM];
__device__ __nv_bfloat16 g_ol[DM * DM];

// ---------------------------------------------------------------------------
// PTX helpers
// ---------------------------------------------------------------------------
#define MMA_BF16(d, a, b) asm volatile( \
  "mma.sync.aligned.m16n8k16.row.col.f32.bf16.bf16.f32 " \
  "{%0,%1,%2,%3}, {%4,%5,%6,%7}, {%8,%9}, {%0,%1,%2,%3};\n" \
  : "+f"((d)[0]), "+f"((d)[1]), "+f"((d)[2]), "+f"((d)[3]) \
  : "r"((a)[0]), "r"((a)[1]), "r"((a)[2]), "r"((a)[3]), \
    "r"((b)[0]), "r"((b)[1]))

#define LDSM4(r0, r1, r2, r3, addr) asm volatile( \
  "ldmatrix.sync.aligned.m8n8.x4.shared.b16 {%0,%1,%2,%3}, [%4];\n" \
  : "=r"(r0), "=r"(r1), "=r"(r2), "=r"(r3) : "r"(addr))

__device__ __forceinline__ void split2(float x, float y, uint32_t& hi, uint32_t& lo)
{
    __nv_bfloat16 hx = __float2bfloat16(x);
    __nv_bfloat16 hy = __float2bfloat16(y);
    __nv_bfloat16 lx = __float2bfloat16(x - __bfloat162float(hx));
    __nv_bfloat16 ly = __float2bfloat16(y - __bfloat162float(hy));
    hi = (uint32_t)__bfloat16_as_ushort(hx) | ((uint32_t)__bfloat16_as_ushort(hy) << 16);
    lo = (uint32_t)__bfloat16_as_ushort(lx) | ((uint32_t)__bfloat16_as_ushort(ly) << 16);
}

// ---------------------------------------------------------------------------
// fp32 -> bf16 hi/lo split
// ---------------------------------------------------------------------------
__global__ void split_bf16(const float4* __restrict__ x,
                           uint2* __restrict__ hi, uint2* __restrict__ lo, int n4)
{
    int i = blockIdx.x * blockDim.x + threadIdx.x;
    if (i >= n4) return;
    float4 v = x[i];
    uint32_t h0, l0, h1, l1;
    split2(v.x, v.y, h0, l0);
    split2(v.z, v.w, h1, l1);
    hi[i] = make_uint2(h0, h1);
    lo[i] = make_uint2(l0, l1);
}

// ---------------------------------------------------------------------------
// NT GEMM: C = Ah*Bh^T + Ah*Bl^T + Al*Bh^T + bias
// CTA tile 128x128, BK=32, STATIC smem (40KB), ldmatrix.x4 fragment loads.
// 8 warps (2x4), warp tile 64x32. No dynamic smem, no cudaFuncSetAttribute.
// ---------------------------------------------------------------------------
#define GSTR 40    // smem row stride in bf16; ldmatrix row offsets i*80B mod 128 all distinct

__global__ __launch_bounds__(256) void gemm_bf16_mma(
    const __nv_bfloat16* __restrict__ Ah, const __nv_bfloat16* __restrict__ Al,
    const __nv_bfloat16* __restrict__ Bh, const __nv_bfloat16* __restrict__ Bl,
    const float* __restrict__ bias, float* __restrict__ C,
    int M, int N, int K)
{
    __shared__ __nv_bfloat16 sAh[128][GSTR], sAl[128][GSTR];
    __shared__ __nv_bfloat16 sBh[128][GSTR], sBl[128][GSTR];

    const int t    = threadIdx.x;
    const int lane = t & 31;
    const int warp = t >> 5;
    const int g    = lane >> 2;
    const int tg   = lane & 3;
    const int wm   = warp >> 2;
    const int wn   = warp & 3;
    const int bm   = blockIdx.x * 128, bn = blockIdx.y * 128;

    const int lr = t >> 1;            // 0..127
    const int lc = (t & 1) * 16;      // 0 or 16 (bf16)

    float acc[4][4][4] = {};

    const __nv_bfloat16* pAh = Ah + (size_t)(bm + lr) * K + lc;
    const __nv_bfloat16* pAl = Al + (size_t)(bm + lr) * K + lc;
    const __nv_bfloat16* pBh = Bh + (size_t)(bn + lr) * K + lc;
    const __nv_bfloat16* pBl = Bl + (size_t)(bn + lr) * K + lc;

    // ldmatrix per-lane address components
    const uint32_t aBase  = (uint32_t)__cvta_generic_to_shared(&sAh[0][0]);
    const uint32_t alBase = (uint32_t)__cvta_generic_to_shared(&sAl[0][0]);
    const uint32_t bBase  = (uint32_t)__cvta_generic_to_shared(&sBh[0][0]);
    const uint32_t blBase = (uint32_t)__cvta_generic_to_shared(&sBl[0][0]);
    const int arow = wm * 64 + (lane & 15);
    const int acol = (lane >> 4) * 8;
    const int brow = wn * 32 + (lane & 7) + ((lane >> 4) * 8);
    const int bcol = ((lane >> 3) & 1) * 8;

    for (int kc = 0; kc < K; kc += 32) {
        *(uint4*)&sAh[lr][lc]     = *(const uint4*)(pAh + kc);
        *(uint4*)&sAh[lr][lc + 8] = *(const uint4*)(pAh + kc + 8);
        *(uint4*)&sAl[lr][lc]     = *(const uint4*)(pAl + kc);
        *(uint4*)&sAl[lr][lc + 8] = *(const uint4*)(pAl + kc + 8);
        *(uint4*)&sBh[lr][lc]     = *(const uint4*)(pBh + kc);
        *(uint4*)&sBh[lr][lc + 8] = *(const uint4*)(pBh + kc + 8);
        *(uint4*)&sBl[lr][lc]     = *(const uint4*)(pBl + kc);
        *(uint4*)&sBl[lr][lc + 8] = *(const uint4*)(pBl + kc + 8);
        __syncthreads();

        #pragma unroll
        for (int ks = 0; ks < 2; ks++) {
            const int kof = ks * 16;
            uint32_t ah[4][4], al[4][4], bh[4][2], bl[4][2];
            #pragma unroll
            for (int mt = 0; mt < 4; mt++) {
                uint32_t off = (uint32_t)((arow + mt * 16) * GSTR + kof + acol) * 2;
                LDSM4(ah[mt][0], ah[mt][1], ah[mt][2], ah[mt][3], aBase + off);
                LDSM4(al[mt][0], al[mt][1], al[mt][2], al[mt][3], alBase + off);
            }
            #pragma unroll
            for (int np = 0; np < 2; np++) {
                uint32_t off = (uint32_t)((brow + np * 16) * GSTR + kof + bcol) * 2;
                LDSM4(bh[2*np][0], bh[2*np][1], bh[2*np+1][0], bh[2*np+1][1], bBase + off);
                LDSM4(bl[2*np][0], bl[2*np][1], bl[2*np+1][0], bl[2*np+1][1], blBase + off);
            }
            #pragma unroll
            for (int mt = 0; mt < 4; mt++)
                #pragma unroll
                for (int nt = 0; nt < 4; nt++) {
                    MMA_BF16(acc[mt][nt], ah[mt], bh[nt]);
                    MMA_BF16(acc[mt][nt], ah[mt], bl[nt]);
                    MMA_BF16(acc[mt][nt], al[mt], bh[nt]);
                }
        }
        __syncthreads();
    }

    // epilogue with bias
    #pragma unroll
    for (int mt = 0; mt < 4; mt++) {
        int row = bm + wm * 64 + mt * 16 + g;
        #pragma unroll
        for (int nt = 0; nt < 4; nt++) {
            int col = bn + wn * 32 + nt * 8 + tg * 2;
            float2 b2 = *(const float2*)&bias[col];
            float2 o0 = {acc[mt][nt][0] + b2.x, acc[mt][nt][1] + b2.y};
            float2 o1 = {acc[mt][nt][2] + b2.x, acc[mt][nt][3] + b2.y};
            *(float2*)&C[(size_t)row * N + col]       = o0;
            *(float2*)&C[(size_t)(row + 8) * N + col] = o1;
        }
    }
}

// ---------------------------------------------------------------------------
// Suffix sums of V per head
// ---------------------------------------------------------------------------
__global__ void sfx1(const float* __restrict__ vp, float* __restrict__ sv,
                     float* __restrict__ csum)
{
    int g = blockIdx.x, c = blockIdx.y, d = threadIdx.x;
    const float* v = vp + (size_t)g * L_SEQ * HD;
    float* s = sv + (size_t)g * (L_SEQ + 1) * HD;
    float a = 0.f;
    #pragma unroll 8
    for (int j = (c + 1) * 256 - 1; j >= c * 256; j--) {
        a += v[j * HD + d];
        s[j * HD + d] = a;
    }
    csum[(g * 8 + c) * HD + d] = a;
}

__global__ void sfx2(float* __restrict__ sv, const float* __restrict__ csum)
{
    int g = blockIdx.x, c = blockIdx.y, d = threadIdx.x;
    float* s = sv + (size_t)g * (L_SEQ + 1) * HD;
    if (c == 7) { s[L_SEQ * HD + d] = 0.f; return; }
    float off = 0.f;
    for (int c2 = c + 1; c2 < 8; c2++) off += csum[(g * 8 + c2) * HD + d];
    #pragma unroll 8
    for (int j = c * 256; j < (c + 1) * 256; j++)
        s[j * HD + d] += off;
}

// ---------------------------------------------------------------------------
// Tensor-core flash attention (validated R10). Unchanged.
// ---------------------------------------------------------------------------
#define ASTR 72

__global__ __launch_bounds__(128) void attn_mma(
    const float* __restrict__ qp, const float* __restrict__ kp,
    const float* __restrict__ vp, const float* __restrict__ sv,
    __nv_bfloat16* __restrict__ ch, __nv_bfloat16* __restrict__ cl)
{
    const int g  = blockIdx.y;
    const int qi = 31 - blockIdx.x;      // big tiles launch first
    const int i0 = qi * 64;
    const float* Qg = qp + (size_t)g * L_SEQ * HD;
    const float* Kg = kp + (size_t)g * L_SEQ * HD;
    const float* Vg = vp + (size_t)g * L_SEQ * HD;
    const float* svg = sv + (size_t)g * (L_SEQ + 1) * HD;

    __shared__ __nv_bfloat16 Kh[64][ASTR], Kl[64][ASTR];
    __shared__ __nv_bfloat16 Vh[64][ASTR], Vl[64][ASTR];   // transposed [d][key]

    const int t    = threadIdx.x;
    const int lane = t & 31;
    const int warp = t >> 5;
    const int gq   = lane >> 2;
    const int tg   = lane & 3;

    const int r0g = i0 + warp * 16 + gq;
    const int r1g = r0g + 8;

    // Q fragments -> registers
    uint32_t qah[4][4], qal[4][4];
    #pragma unroll
    for (int kc = 0; kc < 4; kc++) {
        const int kof = kc * 16 + tg * 2;
        float2 q00 = *(const float2*)&Qg[(size_t)r0g * HD + kof];
        float2 q10 = *(const float2*)&Qg[(size_t)r1g * HD + kof];
        float2 q01 = *(const float2*)&Qg[(size_t)r0g * HD + kof + 8];
        float2 q11 = *(const float2*)&Qg[(size_t)r1g * HD + kof + 8];
        split2(q00.x, q00.y, qah[kc][0], qal[kc][0]);
        split2(q10.x, q10.y, qah[kc][1], qal[kc][1]);
        split2(q01.x, q01.y, qah[kc][2], qal[kc][2]);
        split2(q11.x, q11.y, qah[kc][3], qal[kc][3]);
    }

    float oacc[8][4] = {};
    float m0 = -1e30f, m1 = -1e30f, l0s = 0.f, l1s = 0.f;

    for (int kb = 0; kb <= qi; kb++) {
        const int j0 = kb * 64;
        #pragma unroll
        for (int rep = 0; rep < 8; rep++) {
            int idx = t + rep * 128;
            int r = idx >> 4, d4 = (idx & 15) * 4;
            float4 kv = *(const float4*)&Kg[(size_t)(j0 + r) * HD + d4];
            uint32_t h0, l0, h1, l1;
            split2(kv.x, kv.y, h0, l0);
            split2(kv.z, kv.w, h1, l1);
            *(uint32_t*)&Kh[r][d4]     = h0;  *(uint32_t*)&Kh[r][d4 + 2] = h1;
            *(uint32_t*)&Kl[r][d4]     = l0;  *(uint32_t*)&Kl[r][d4 + 2] = l1;
            float4 vv = *(const float4*)&Vg[(size_t)(j0 + r) * HD + d4];
            float va[4] = {vv.x, vv.y, vv.z, vv.w};
            #pragma unroll
            for (int j = 0; j < 4; j++) {
                __nv_bfloat16 h = __float2bfloat16(va[j]);
                __nv_bfloat16 l = __float2bfloat16(va[j] - __bfloat162float(h));
                Vh[d4 + j][r] = h;
                Vl[d4 + j][r] = l;
            }
        }
        __syncthreads();

        float sacc[8][4] = {};
        #pragma unroll
        for (int kc = 0; kc < 4; kc++) {
            const int kof = kc * 16 + tg * 2;
            #pragma unroll
            for (int nt = 0; nt < 8; nt++) {
                uint32_t bh[2], bl[2];
                bh[0] = *(const uint32_t*)&Kh[nt * 8 + gq][kof];
                bh[1] = *(const uint32_t*)&Kh[nt * 8 + gq][kof + 8];
                bl[0] = *(const uint32_t*)&Kl[nt * 8 + gq][kof];
                bl[1] = *(const uint32_t*)&Kl[nt * 8 + gq][kof + 8];
                MMA_BF16(sacc[nt], qah[kc], bh);
                MMA_BF16(sacc[nt], qah[kc], bl);
                MMA_BF16(sacc[nt], qal[kc], bh);
            }
        }

        #pragma unroll
        for (int nt = 0; nt < 8; nt++) {
            int c0 = j0 + nt * 8 + tg * 2, c1 = c0 + 1;
            sacc[nt][0] = (c0 > r0g) ? -1e30f : sacc[nt][0] * 0.125f;
            sacc[nt][1] = (c1 > r0g) ? -1e30f : sacc[nt][1] * 0.125f;
            sacc[nt][2] = (c0 > r1g) ? -1e30f : sacc[nt][2] * 0.125f;
            sacc[nt][3] = (c1 > r1g) ? -1e30f : sacc[nt][3] * 0.125f;
        }

        float mx0 = -1e30f, mx1 = -1e30f;
        #pragma unroll
        for (int nt = 0; nt < 8; nt++) {
            mx0 = fmaxf(mx0, fmaxf(sacc[nt][0], sacc[nt][1]));
            mx1 = fmaxf(mx1, fmaxf(sacc[nt][2], sacc[nt][3]));
        }
        mx0 = fmaxf(mx0, __shfl_xor_sync(0xffffffffu, mx0, 1));
        mx0 = fmaxf(mx0, __shfl_xor_sync(0xffffffffu, mx0, 2));
        mx1 = fmaxf(mx1, __shfl_xor_sync(0xffffffffu, mx1, 1));
        mx1 = fmaxf(mx1, __shfl_xor_sync(0xffffffffu, mx1, 2));
        float mn0 = fmaxf(m0, mx0), mn1 = fmaxf(m1, mx1);
        float sc0 = __expf(m0 - mn0), sc1 = __expf(m1 - mn1);
        m0 = mn0; m1 = mn1;

        uint32_t pah[4][4], pal[4][4];
        float ls0 = 0.f, ls1 = 0.f;
        #pragma unroll
        for (int c = 0; c < 4; c++) {
            float p00 = __expf(sacc[2*c  ][0] - mn0), p01 = __expf(sacc[2*c  ][1] - mn0);
            float p10 = __expf(sacc[2*c  ][2] - mn1), p11 = __expf(sacc[2*c  ][3] - mn1);
            float p20 = __expf(sacc[2*c+1][0] - mn0), p21 = __expf(sacc[2*c+1][1] - mn0);
            float p30 = __expf(sacc[2*c+1][2] - mn1), p31 = __expf(sacc[2*c+1][3] - mn1);
            ls0 += p00 + p01 + p20 + p21;
            ls1 += p10 + p11 + p30 + p31;
            split2(p00, p01, pah[c][0], pal[c][0]);
            split2(p10, p11, pah[c][1], pal[c][1]);
            split2(p20, p21, pah[c][2], pal[c][2]);
            split2(p30, p31, pah[c][3], pal[c][3]);
        }
        ls0 += __shfl_xor_sync(0xffffffffu, ls0, 1);
        ls0 += __shfl_xor_sync(0xffffffffu, ls0, 2);
        ls1 += __shfl_xor_sync(0xffffffffu, ls1, 1);
        ls1 += __shfl_xor_sync(0xffffffffu, ls1, 2);
        l0s = l0s * sc0 + ls0;
        l1s = l1s * sc1 + ls1;

        #pragma unroll
        for (int dn = 0; dn < 8; dn++) {
            oacc[dn][0] *= sc0; oacc[dn][1] *= sc0;
            oacc[dn][2] *= sc1; oacc[dn][3] *= sc1;
        }

        #pragma unroll
        for (int c = 0; c < 4; c++) {
            const int kof = c * 16 + tg * 2;
            #pragma unroll
            for (int dn = 0; dn < 8; dn++) {
                uint32_t vh[2], vl[2];
                vh[0] = *(const uint32_t*)&Vh[dn * 8 + gq][kof];
                vh[1] = *(const uint32_t*)&Vh[dn * 8 + gq][kof + 8];
                vl[0] = *(const uint32_t*)&Vl[dn * 8 + gq][kof];
                vl[1] = *(const uint32_t*)&Vl[dn * 8 + gq][kof + 8];
                MMA_BF16(oacc[dn], pah[c], vh);
                MMA_BF16(oacc[dn], pah[c], vl);
                MMA_BF16(oacc[dn], pal[c], vh);
            }
        }
        __syncthreads();
    }

    float mf0 = fmaxf(m0, 0.f), mf1 = fmaxf(m1, 0.f);
    float ez0 = __expf(-mf0), ez1 = __expf(-mf1);
    float fc0 = __expf(m0 - mf0), fc1 = __expf(m1 - mf1);
    float inv0 = 1.f / (l0s * fc0 + (float)(L_SEQ - 1 - r0g) * ez0);
    float inv1 = 1.f / (l1s * fc1 + (float)(L_SEQ - 1 - r1g) * ez1);

    const size_t base = (size_t)g * L_SEQ * HD;
    #pragma unroll
    for (int dn = 0; dn < 8; dn++) {
        int d = dn * 8 + tg * 2;
        float2 s0 = *(const float2*)&svg[(size_t)(r0g + 1) * HD + d];
        float2 s1 = *(const float2*)&svg[(size_t)(r1g + 1) * HD + d];
        float o00 = (oacc[dn][0] * fc0 + ez0 * s0.x) * inv0;
        float o01 = (oacc[dn][1] * fc0 + ez0 * s0.y) * inv0;
        float o10 = (oacc[dn][2] * fc1 + ez1 * s1.x) * inv1;
        float o11 = (oacc[dn][3] * fc1 + ez1 * s1.y) * inv1;
        uint32_t h, l;
        split2(o00, o01, h, l);
        *(uint32_t*)&ch[base + (size_t)r0g * HD + d] = h;
        *(uint32_t*)&cl[base + (size_t)r0g * HD + d] = l;
        split2(o10, o11, h, l);
        *(uint32_t*)&ch[base + (size_t)r1g * HD + d] = h;
        *(uint32_t*)&cl[base + (size_t)r1g * HD + d] = l;
    }
}

// ---------------------------------------------------------------------------
extern "C" void kernel_launch(void* const* d_in, const int* in_sizes, int n_in,
                              void* d_out, int out_size)
{
    const float* q     = (const float*)d_in[0];
    const float* k     = (const float*)d_in[1];
    const float* v     = (const float*)d_in[2];
    // d_in[3] = attn_mask (causal by construction; handled analytically)
    const float* wq_w  = (const float*)d_in[4];
    const float* wq_b  = (const float*)d_in[5];
    const float* out_w = (const float*)d_in[6];
    const float* out_b = (const float*)d_in[7];
    float* out = (float*)d_out;

    float *qkvp, *sv, *csum;
    __nv_bfloat16 *ah, *al, *wh, *wl, *oh, *ol;
    cudaGetSymbolAddress((void**)&qkvp, g_qkvp);
    cudaGetSymbolAddress((void**)&sv,   g_sv);
    cudaGetSymbolAddress((void**)&csum, g_csum);
    cudaGetSymbolAddress((void**)&ah,   g_ah);
    cudaGetSymbolAddress((void**)&al,   g_al);
    cudaGetSymbolAddress((void**)&wh,   g_wh);
    cudaGetSymbolAddress((void**)&wl,   g_wl);
    cudaGetSymbolAddress((void**)&oh,   g_oh);
    cudaGetSymbolAddress((void**)&ol,   g_ol);

    const int NA4 = MTOT * DM / 4;
    const int NW4 = DM * DM / 4;
    const size_t MD = (size_t)MTOT * DM;

    float* qp = qkvp;
    float* kp = qkvp + MD;
    float* vp = qkvp + 2 * MD;

    // weight splits
    split_bf16<<<(NW4 + 255) / 256, 256>>>((const float4*)wq_w,  (uint2*)wh, (uint2*)wl, NW4);
    split_bf16<<<(NW4 + 255) / 256, 256>>>((const float4*)out_w, (uint2*)oh, (uint2*)ol, NW4);

    // input splits into one contiguous q|k|v buffer
    split_bf16<<<(NA4 + 255) / 256, 256>>>((const float4*)q,
        (uint2*)ah, (uint2*)al, NA4);
    split_bf16<<<(NA4 + 255) / 256, 256>>>((const float4*)k,
        (uint2*)(ah + MD), (uint2*)(al + MD), NA4);
    split_bf16<<<(NA4 + 255) / 256, 256>>>((const float4*)v,
        (uint2*)(ah + 2 * MD), (uint2*)(al + 2 * MD), NA4);

    // fused QKV projection: one GEMM, M = 3*4096
    gemm_bf16_mma<<<dim3(3 * MTOT / 128, DM / 128), 256>>>(
        ah, al, wh, wl, wq_b, qkvp, 3 * MTOT, DM, DM);

    sfx1<<<dim3(NG, 8), HD>>>(vp, sv, csum);
    sfx2<<<dim3(NG, 8), HD>>>(sv, csum);

    // tensor-core attention; writes ctx directly as bf16 hi/lo into ah/al
    attn_mma<<<dim3(L_SEQ / 64, NG), 128>>>(qp, kp, vp, sv, ah, al);

    // output projection
    gemm_bf16_mma<<<dim3(MTOT / 128, DM / 128), 256>>>(
        ah, al, oh, ol, out_b, out, MTOT, DM, DM);
}

// round 15
// speedup vs baseline: 2.4054x; 1.1045x over previous
#include <cuda_runtime.h>
#include <cuda_bf16.h>
#include <cstdint>

#define L_SEQ 2048
#define DM 1024
#define HD 64
#define NG 32            // b * n_head after buggy reshape = 2*16
#define MTOT 4096        // B * L

// ---------------------------------------------------------------------------
// Scratch (static device globals -- no allocation allowed)
// ---------------------------------------------------------------------------
__device__ float g_qkvp[3 * MTOT * DM];          // projected q|k|v (contiguous)
__device__ float g_sv[NG * (L_SEQ + 1) * HD];    // suffix sums of V per head
__device__ float g_csum[NG * 32 * HD];
// bf16 hi/lo split buffers (holds q|k|v splits, later reused for ctx)
__device__ __nv_bfloat16 g_ah[3 * MTOT * DM];
__device__ __nv_bfloat16 g_al[3 * MTOT * DM];
__device__ __nv_bfloat16 g_wh[DM * DM];
__device__ __nv_bfloat16 g_wl[DM * DM];
__device__ __nv_bfloat16 g_oh[DM * DM];
__device__ __nv_bfloat16 g_ol[DM * DM];

// ---------------------------------------------------------------------------
// PTX helpers (NO cp.async -- empirically kills the harness container)
// ---------------------------------------------------------------------------
#define MMA_BF16(d, a, b) asm volatile( \
  "mma.sync.aligned.m16n8k16.row.col.f32.bf16.bf16.f32 " \
  "{%0,%1,%2,%3}, {%4,%5,%6,%7}, {%8,%9}, {%0,%1,%2,%3};\n" \
  : "+f"((d)[0]), "+f"((d)[1]), "+f"((d)[2]), "+f"((d)[3]) \
  : "r"((a)[0]), "r"((a)[1]), "r"((a)[2]), "r"((a)[3]), \
    "r"((b)[0]), "r"((b)[1]))

#define LDSM4(r0, r1, r2, r3, addr) asm volatile( \
  "ldmatrix.sync.aligned.m8n8.x4.shared.b16 {%0,%1,%2,%3}, [%4];\n" \
  : "=r"(r0), "=r"(r1), "=r"(r2), "=r"(r3) : "r"(addr))

__device__ __forceinline__ void split2(float x, float y, uint32_t& hi, uint32_t& lo)
{
    __nv_bfloat16 hx = __float2bfloat16(x);
    __nv_bfloat16 hy = __float2bfloat16(y);
    __nv_bfloat16 lx = __float2bfloat16(x - __bfloat162float(hx));
    __nv_bfloat16 ly = __float2bfloat16(y - __bfloat162float(hy));
    hi = (uint32_t)__bfloat16_as_ushort(hx) | ((uint32_t)__bfloat16_as_ushort(hy) << 16);
    lo = (uint32_t)__bfloat16_as_ushort(lx) | ((uint32_t)__bfloat16_as_ushort(ly) << 16);
}

// ---------------------------------------------------------------------------
// fp32 -> bf16 hi/lo split
// ---------------------------------------------------------------------------
__global__ void split_bf16(const float4* __restrict__ x,
                           uint2* __restrict__ hi, uint2* __restrict__ lo, int n4)
{
    int i = blockIdx.x * blockDim.x + threadIdx.x;
    if (i >= n4) return;
    float4 v = x[i];
    uint32_t h0, l0, h1, l1;
    split2(v.x, v.y, h0, l0);
    split2(v.z, v.w, h1, l1);
    hi[i] = make_uint2(h0, h1);
    lo[i] = make_uint2(l0, l1);
}

// ---------------------------------------------------------------------------
// NT GEMM: C = Ah*Bh^T + Ah*Bl^T + Al*Bh^T + bias
// CTA tile 128x128, BK=32, STATIC 40KB smem, ldmatrix.x4 fragment loads,
// REGISTER-PREFETCH pipeline: LDGs for chunk kc+1 issued before the MMA block
// of chunk kc (overlaps gmem latency with tensor work; no cp.async).
// 8 warps (2x4), warp tile 64x32.
// ---------------------------------------------------------------------------
#define GSTR 40    // smem row stride in bf16; ldmatrix row offsets i*80B mod 128 all distinct

__global__ __launch_bounds__(256) void gemm_bf16_mma(
    const __nv_bfloat16* __restrict__ Ah, const __nv_bfloat16* __restrict__ Al,
    const __nv_bfloat16* __restrict__ Bh, const __nv_bfloat16* __restrict__ Bl,
    const float* __restrict__ bias, float* __restrict__ C,
    int M, int N, int K)
{
    __shared__ __nv_bfloat16 sAh[128][GSTR], sAl[128][GSTR];
    __shared__ __nv_bfloat16 sBh[128][GSTR], sBl[128][GSTR];

    const int t    = threadIdx.x;
    const int lane = t & 31;
    const int warp = t >> 5;
    const int g    = lane >> 2;
    const int tg   = lane & 3;
    const int wm   = warp >> 2;
    const int wn   = warp & 3;
    const int bm   = blockIdx.x * 128, bn = blockIdx.y * 128;

    const int lr = t >> 1;            // 0..127
    const int lc = (t & 1) * 16;      // 0 or 16 (bf16)

    float acc[4][4][4] = {};

    const __nv_bfloat16* pAh = Ah + (size_t)(bm + lr) * K + lc;
    const __nv_bfloat16* pAl = Al + (size_t)(bm + lr) * K + lc;
    const __nv_bfloat16* pBh = Bh + (size_t)(bn + lr) * K + lc;
    const __nv_bfloat16* pBl = Bl + (size_t)(bn + lr) * K + lc;

    // ldmatrix per-lane address components
    const uint32_t aBase  = (uint32_t)__cvta_generic_to_shared(&sAh[0][0]);
    const uint32_t alBase = (uint32_t)__cvta_generic_to_shared(&sAl[0][0]);
    const uint32_t bBase  = (uint32_t)__cvta_generic_to_shared(&sBh[0][0]);
    const uint32_t blBase = (uint32_t)__cvta_generic_to_shared(&sBl[0][0]);
    const int arow = wm * 64 + (lane & 15);
    const int acol = (lane >> 4) * 8;
    const int brow = wn * 32 + (lane & 7) + ((lane >> 4) * 8);
    const int bcol = ((lane >> 3) & 1) * 8;

    // register staging for the gmem->smem pipeline
    uint4 rAh0, rAh1, rAl0, rAl1, rBh0, rBh1, rBl0, rBl1;
    auto ldreg = [&](int kc) {
        rAh0 = *(const uint4*)(pAh + kc);  rAh1 = *(const uint4*)(pAh + kc + 8);
        rAl0 = *(const uint4*)(pAl + kc);  rAl1 = *(const uint4*)(pAl + kc + 8);
        rBh0 = *(const uint4*)(pBh + kc);  rBh1 = *(const uint4*)(pBh + kc + 8);
        rBl0 = *(const uint4*)(pBl + kc);  rBl1 = *(const uint4*)(pBl + kc + 8);
    };
    ldreg(0);

    for (int kc = 0; kc < K; kc += 32) {
        // drain staged regs into smem
        *(uint4*)&sAh[lr][lc] = rAh0;  *(uint4*)&sAh[lr][lc + 8] = rAh1;
        *(uint4*)&sAl[lr][lc] = rAl0;  *(uint4*)&sAl[lr][lc + 8] = rAl1;
        *(uint4*)&sBh[lr][lc] = rBh0;  *(uint4*)&sBh[lr][lc + 8] = rBh1;
        *(uint4*)&sBl[lr][lc] = rBl0;  *(uint4*)&sBl[lr][lc + 8] = rBl1;
        __syncthreads();

        // issue next chunk's LDGs now; latency hides under the MMAs below
        if (kc + 32 < K) ldreg(kc + 32);

        #pragma unroll
        for (int ks = 0; ks < 2; ks++) {
            const int kof = ks * 16;
            uint32_t ah[4][4], al[4][4], bh[4][2], bl[4][2];
            #pragma unroll
            for (int mt = 0; mt < 4; mt++) {
                uint32_t off = (uint32_t)((arow + mt * 16) * GSTR + kof + acol) * 2;
                LDSM4(ah[mt][0], ah[mt][1], ah[mt][2], ah[mt][3], aBase + off);
                LDSM4(al[mt][0], al[mt][1], al[mt][2], al[mt][3], alBase + off);
            }
            #pragma unroll
            for (int np = 0; np < 2; np++) {
                uint32_t off = (uint32_t)((brow + np * 16) * GSTR + kof + bcol) * 2;
                LDSM4(bh[2*np][0], bh[2*np][1], bh[2*np+1][0], bh[2*np+1][1], bBase + off);
                LDSM4(bl[2*np][0], bl[2*np][1], bl[2*np+1][0], bl[2*np+1][1], blBase + off);
            }
            #pragma unroll
            for (int mt = 0; mt < 4; mt++)
                #pragma unroll
                for (int nt = 0; nt < 4; nt++) {
                    MMA_BF16(acc[mt][nt], ah[mt], bh[nt]);
                    MMA_BF16(acc[mt][nt], ah[mt], bl[nt]);
                    MMA_BF16(acc[mt][nt], al[mt], bh[nt]);
                }
        }
        __syncthreads();
    }

    // epilogue with bias
    #pragma unroll
    for (int mt = 0; mt < 4; mt++) {
        int row = bm + wm * 64 + mt * 16 + g;
        #pragma unroll
        for (int nt = 0; nt < 4; nt++) {
            int col = bn + wn * 32 + nt * 8 + tg * 2;
            float2 b2 = *(const float2*)&bias[col];
            float2 o0 = {acc[mt][nt][0] + b2.x, acc[mt][nt][1] + b2.y};
            float2 o1 = {acc[mt][nt][2] + b2.x, acc[mt][nt][3] + b2.y};
            *(float2*)&C[(size_t)row * N + col]       = o0;
            *(float2*)&C[(size_t)(row + 8) * N + col] = o1;
        }
    }
}

// ---------------------------------------------------------------------------
// Suffix sums of V per head (32 chunks of 64 rows)
// ---------------------------------------------------------------------------
__global__ void sfx1(const float* __restrict__ vp, float* __restrict__ sv,
                     float* __restrict__ csum)
{
    int g = blockIdx.x, c = blockIdx.y, d = threadIdx.x;
    const float* v = vp + (size_t)g * L_SEQ * HD;
    float* s = sv + (size_t)g * (L_SEQ + 1) * HD;
    float a = 0.f;
    #pragma unroll 8
    for (int j = (c + 1) * 64 - 1; j >= c * 64; j--) {
        a += v[j * HD + d];
        s[j * HD + d] = a;
    }
    csum[(g * 32 + c) * HD + d] = a;
}

__global__ void sfx2(float* __restrict__ sv, const float* __restrict__ csum)
{
    int g = blockIdx.x, c = blockIdx.y, d = threadIdx.x;
    float* s = sv + (size_t)g * (L_SEQ + 1) * HD;
    if (c == 31) { s[L_SEQ * HD + d] = 0.f; return; }
    float off = 0.f;
    for (int c2 = c + 1; c2 < 32; c2++) off += csum[(g * 32 + c2) * HD + d];
    #pragma unroll 8
    for (int j = c * 64; j < (c + 1) * 64; j++)
        s[j * HD + d] += off;
}

// ---------------------------------------------------------------------------
// Tensor-core flash attention (validated R10/R13). Unchanged.
// ---------------------------------------------------------------------------
#define ASTR 72

__global__ __launch_bounds__(128) void attn_mma(
    const float* __restrict__ qp, const float* __restrict__ kp,
    const float* __restrict__ vp, const float* __restrict__ sv,
    __nv_bfloat16* __restrict__ ch, __nv_bfloat16* __restrict__ cl)
{
    const int g  = blockIdx.y;
    const int qi = 31 - blockIdx.x;      // big tiles launch first
    const int i0 = qi * 64;
    const float* Qg = qp + (size_t)g * L_SEQ * HD;
    const float* Kg = kp + (size_t)g * L_SEQ * HD;
    const float* Vg = vp + (size_t)g * L_SEQ * HD;
    const float* svg = sv + (size_t)g * (L_SEQ + 1) * HD;

    __shared__ __nv_bfloat16 Kh[64][ASTR], Kl[64][ASTR];
    __shared__ __nv_bfloat16 Vh[64][ASTR], Vl[64][ASTR];   // transposed [d][key]

    const int t    = threadIdx.x;
    const int lane = t & 31;
    const int warp = t >> 5;
    const int gq   = lane >> 2;
    const int tg   = lane & 3;

    const int r0g = i0 + warp * 16 + gq;
    const int r1g = r0g + 8;

    // Q fragments -> registers
    uint32_t qah[4][4], qal[4][4];
    #pragma unroll
    for (int kc = 0; kc < 4; kc++) {
        const int kof = kc * 16 + tg * 2;
        float2 q00 = *(const float2*)&Qg[(size_t)r0g * HD + kof];
        float2 q10 = *(const float2*)&Qg[(size_t)r1g * HD + kof];
        float2 q01 = *(const float2*)&Qg[(size_t)r0g * HD + kof + 8];
        float2 q11 = *(const float2*)&Qg[(size_t)r1g * HD + kof + 8];
        split2(q00.x, q00.y, qah[kc][0], qal[kc][0]);
        split2(q10.x, q10.y, qah[kc][1], qal[kc][1]);
        split2(q01.x, q01.y, qah[kc][2], qal[kc][2]);
        split2(q11.x, q11.y, qah[kc][3], qal[kc][3]);
    }

    float oacc[8][4] = {};
    float m0 = -1e30f, m1 = -1e30f, l0s = 0.f, l1s = 0.f;

    for (int kb = 0; kb <= qi; kb++) {
        const int j0 = kb * 64;
        #pragma unroll
        for (int rep = 0; rep < 8; rep++) {
            int idx = t + rep * 128;
            int r = idx >> 4, d4 = (idx & 15) * 4;
            float4 kv = *(const float4*)&Kg[(size_t)(j0 + r) * HD + d4];
            uint32_t h0, l0, h1, l1;
            split2(kv.x, kv.y, h0, l0);
            split2(kv.z, kv.w, h1, l1);
            *(uint32_t*)&Kh[r][d4]     = h0;  *(uint32_t*)&Kh[r][d4 + 2] = h1;
            *(uint32_t*)&Kl[r][d4]     = l0;  *(uint32_t*)&Kl[r][d4 + 2] = l1;
            float4 vv = *(const float4*)&Vg[(size_t)(j0 + r) * HD + d4];
            float va[4] = {vv.x, vv.y, vv.z, vv.w};
            #pragma unroll
            for (int j = 0; j < 4; j++) {
                __nv_bfloat16 h = __float2bfloat16(va[j]);
                __nv_bfloat16 l = __float2bfloat16(va[j] - __bfloat162float(h));
                Vh[d4 + j][r] = h;
                Vl[d4 + j][r] = l;
            }
        }
        __syncthreads();

        float sacc[8][4] = {};
        #pragma unroll
        for (int kc = 0; kc < 4; kc++) {
            const int kof = kc * 16 + tg * 2;
            #pragma unroll
            for (int nt = 0; nt < 8; nt++) {
                uint32_t bh[2], bl[2];
                bh[0] = *(const uint32_t*)&Kh[nt * 8 + gq][kof];
                bh[1] = *(const uint32_t*)&Kh[nt * 8 + gq][kof + 8];
                bl[0] = *(const uint32_t*)&Kl[nt * 8 + gq][kof];
                bl[1] = *(const uint32_t*)&Kl[nt * 8 + gq][kof + 8];
                MMA_BF16(sacc[nt], qah[kc], bh);
                MMA_BF16(sacc[nt], qah[kc], bl);
                MMA_BF16(sacc[nt], qal[kc], bh);
            }
        }

        #pragma unroll
        for (int nt = 0; nt < 8; nt++) {
            int c0 = j0 + nt * 8 + tg * 2, c1 = c0 + 1;
            sacc[nt][0] = (c0 > r0g) ? -1e30f : sacc[nt][0] * 0.125f;
            sacc[nt][1] = (c1 > r0g) ? -1e30f : sacc[nt][1] * 0.125f;
            sacc[nt][2] = (c0 > r1g) ? -1e30f : sacc[nt][2] * 0.125f;
            sacc[nt][3] = (c1 > r1g) ? -1e30f : sacc[nt][3] * 0.125f;
        }

        float mx0 = -1e30f, mx1 = -1e30f;
        #pragma unroll
        for (int nt = 0; nt < 8; nt++) {
            mx0 = fmaxf(mx0, fmaxf(sacc[nt][0], sacc[nt][1]));
            mx1 = fmaxf(mx1, fmaxf(sacc[nt][2], sacc[nt][3]));
        }
        mx0 = fmaxf(mx0, __shfl_xor_sync(0xffffffffu, mx0, 1));
        mx0 = fmaxf(mx0, __shfl_xor_sync(0xffffffffu, mx0, 2));
        mx1 = fmaxf(mx1, __shfl_xor_sync(0xffffffffu, mx1, 1));
        mx1 = fmaxf(mx1, __shfl_xor_sync(0xffffffffu, mx1, 2));
        float mn0 = fmaxf(m0, mx0), mn1 = fmaxf(m1, mx1);
        float sc0 = __expf(m0 - mn0), sc1 = __expf(m1 - mn1);
        m0 = mn0; m1 = mn1;

        uint32_t pah[4][4], pal[4][4];
        float ls0 = 0.f, ls1 = 0.f;
        #pragma unroll
        for (int c = 0; c < 4; c++) {
            float p00 = __expf(sacc[2*c  ][0] - mn0), p01 = __expf(sacc[2*c  ][1] - mn0);
            float p10 = __expf(sacc[2*c  ][2] - mn1), p11 = __expf(sacc[2*c  ][3] - mn1);
            float p20 = __expf(sacc[2*c+1][0] - mn0), p21 = __expf(sacc[2*c+1][1] - mn0);
            float p30 = __expf(sacc[2*c+1][2] - mn1), p31 = __expf(sacc[2*c+1][3] - mn1);
            ls0 += p00 + p01 + p20 + p21;
            ls1 += p10 + p11 + p30 + p31;
            split2(p00, p01, pah[c][0], pal[c][0]);
            split2(p10, p11, pah[c][1], pal[c][1]);
            split2(p20, p21, pah[c][2], pal[c][2]);
            split2(p30, p31, pah[c][3], pal[c][3]);
        }
        ls0 += __shfl_xor_sync(0xffffffffu, ls0, 1);
        ls0 += __shfl_xor_sync(0xffffffffu, ls0, 2);
        ls1 += __shfl_xor_sync(0xffffffffu, ls1, 1);
        ls1 += __shfl_xor_sync(0xffffffffu, ls1, 2);
        l0s = l0s * sc0 + ls0;
        l1s = l1s * sc1 + ls1;

        #pragma unroll
        for (int dn = 0; dn < 8; dn++) {
            oacc[dn][0] *= sc0; oacc[dn][1] *= sc0;
            oacc[dn][2] *= sc1; oacc[dn][3] *= sc1;
        }

        #pragma unroll
        for (int c = 0; c < 4; c++) {
            const int kof = c * 16 + tg * 2;
            #pragma unroll
            for (int dn = 0; dn < 8; dn++) {
                uint32_t vh[2], vl[2];
                vh[0] = *(const uint32_t*)&Vh[dn * 8 + gq][kof];
                vh[1] = *(const uint32_t*)&Vh[dn * 8 + gq][kof + 8];
                vl[0] = *(const uint32_t*)&Vl[dn * 8 + gq][kof];
                vl[1] = *(const uint32_t*)&Vl[dn * 8 + gq][kof + 8];
                MMA_BF16(oacc[dn], pah[c], vh);
                MMA_BF16(oacc[dn], pah[c], vl);
                MMA_BF16(oacc[dn], pal[c], vh);
            }
        }
        __syncthreads();
    }

    float mf0 = fmaxf(m0, 0.f), mf1 = fmaxf(m1, 0.f);
    float ez0 = __expf(-mf0), ez1 = __expf(-mf1);
    float fc0 = __expf(m0 - mf0), fc1 = __expf(m1 - mf1);
    float inv0 = 1.f / (l0s * fc0 + (float)(L_SEQ - 1 - r0g) * ez0);
    float inv1 = 1.f / (l1s * fc1 + (float)(L_SEQ - 1 - r1g) * ez1);

    const size_t base = (size_t)g * L_SEQ * HD;
    #pragma unroll
    for (int dn = 0; dn < 8; dn++) {
        int d = dn * 8 + tg * 2;
        float2 s0 = *(const float2*)&svg[(size_t)(r0g + 1) * HD + d];
        float2 s1 = *(const float2*)&svg[(size_t)(r1g + 1) * HD + d];
        float o00 = (oacc[dn][0] * fc0 + ez0 * s0.x) * inv0;
        float o01 = (oacc[dn][1] * fc0 + ez0 * s0.y) * inv0;
        float o10 = (oacc[dn][2] * fc1 + ez1 * s1.x) * inv1;
        float o11 = (oacc[dn][3] * fc1 + ez1 * s1.y) * inv1;
        uint32_t h, l;
        split2(o00, o01, h, l);
        *(uint32_t*)&ch[base + (size_t)r0g * HD + d] = h;
        *(uint32_t*)&cl[base + (size_t)r0g * HD + d] = l;
        split2(o10, o11, h, l);
        *(uint32_t*)&ch[base + (size_t)r1g * HD + d] = h;
        *(uint32_t*)&cl[base + (size_t)r1g * HD + d] = l;
    }
}

// ---------------------------------------------------------------------------
extern "C" void kernel_launch(void* const* d_in, const int* in_sizes, int n_in,
                              void* d_out, int out_size)
{
    const float* q     = (const float*)d_in[0];
    const float* k     = (const float*)d_in[1];
    const float* v     = (const float*)d_in[2];
    // d_in[3] = attn_mask (causal by construction; handled analytically)
    const float* wq_w  = (const float*)d_in[4];
    const float* wq_b  = (const float*)d_in[5];
    const float* out_w = (const float*)d_in[6];
    const float* out_b = (const float*)d_in[7];
    float* out = (float*)d_out;

    float *qkvp, *sv, *csum;
    __nv_bfloat16 *ah, *al, *wh, *wl, *oh, *ol;
    cudaGetSymbolAddress((void**)&qkvp, g_qkvp);
    cudaGetSymbolAddress((void**)&sv,   g_sv);
    cudaGetSymbolAddress((void**)&csum, g_csum);
    cudaGetSymbolAddress((void**)&ah,   g_ah);
    cudaGetSymbolAddress((void**)&al,   g_al);
    cudaGetSymbolAddress((void**)&wh,   g_wh);
    cudaGetSymbolAddress((void**)&wl,   g_wl);
    cudaGetSymbolAddress((void**)&oh,   g_oh);
    cudaGetSymbolAddress((void**)&ol,   g_ol);

    const int NA4 = MTOT * DM / 4;
    const int NW4 = DM * DM / 4;
    const size_t MD = (size_t)MTOT * DM;

    float* qp = qkvp;
    float* kp = qkvp + MD;
    float* vp = qkvp + 2 * MD;

    // weight splits
    split_bf16<<<(NW4 + 255) / 256, 256>>>((const float4*)wq_w,  (uint2*)wh, (uint2*)wl, NW4);
    split_bf16<<<(NW4 + 255) / 256, 256>>>((const float4*)out_w, (uint2*)oh, (uint2*)ol, NW4);

    // input splits into one contiguous q|k|v buffer
    split_bf16<<<(NA4 + 255) / 256, 256>>>((const float4*)q,
        (uint2*)ah, (uint2*)al, NA4);
    split_bf16<<<(NA4 + 255) / 256, 256>>>((const float4*)k,
        (uint2*)(ah + MD), (uint2*)(al + MD), NA4);
    split_bf16<<<(NA4 + 255) / 256, 256>>>((const float4*)v,
        (uint2*)(ah + 2 * MD), (uint2*)(al + 2 * MD), NA4);

    // fused QKV projection: one GEMM, M = 3*4096
    gemm_bf16_mma<<<dim3(3 * MTOT / 128, DM / 128), 256>>>(
        ah, al, wh, wl, wq_b, qkvp, 3 * MTOT, DM, DM);

    sfx1<<<dim3(NG, 32), HD>>>(vp, sv, csum);
    sfx2<<<dim3(NG, 32), HD>>>(sv, csum);

    // tensor-core attention; writes ctx directly as bf16 hi/lo into ah/al
    attn_mma<<<dim3(L_SEQ / 64, NG), 128>>>(qp, kp, vp, sv, ah, al);

    // output projection
    gemm_bf16_mma<<<dim3(MTOT / 128, DM / 128), 256>>>(
        ah, al, oh, ol, out_b, out, MTOT, DM, DM);
}

// round 16
// speedup vs baseline: 2.4121x; 1.0028x over previous
#include <cuda_runtime.h>
#include <cuda_bf16.h>
#include <cstdint>

#define L_SEQ 2048
#define DM 1024
#define HD 64
#define NG 32            // b * n_head after buggy reshape = 2*16
#define MTOT 4096        // B * L

// ---------------------------------------------------------------------------
// Scratch (static device globals -- no allocation allowed)
// ---------------------------------------------------------------------------
__device__ float g_qkvp[3 * MTOT * DM];          // projected q|k|v (contiguous)
__device__ float g_sv[NG * (L_SEQ + 1) * HD];    // suffix sums of V per head
__device__ float g_csum[NG * 32 * HD];
// bf16 hi/lo split buffers (holds q|k|v splits, later reused for ctx)
__device__ __nv_bfloat16 g_ah[3 * MTOT * DM];
__device__ __nv_bfloat16 g_al[3 * MTOT * DM];
__device__ __nv_bfloat16 g_wh[DM * DM];
__device__ __nv_bfloat16 g_wl[DM * DM];
__device__ __nv_bfloat16 g_oh[DM * DM];
__device__ __nv_bfloat16 g_ol[DM * DM];

// ---------------------------------------------------------------------------
// PTX helpers (NO cp.async -- empirically kills the harness container)
// ---------------------------------------------------------------------------
#define MMA_BF16(d, a, b) asm volatile( \
  "mma.sync.aligned.m16n8k16.row.col.f32.bf16.bf16.f32 " \
  "{%0,%1,%2,%3}, {%4,%5,%6,%7}, {%8,%9}, {%0,%1,%2,%3};\n" \
  : "+f"((d)[0]), "+f"((d)[1]), "+f"((d)[2]), "+f"((d)[3]) \
  : "r"((a)[0]), "r"((a)[1]), "r"((a)[2]), "r"((a)[3]), \
    "r"((b)[0]), "r"((b)[1]))

#define LDSM4(r0, r1, r2, r3, addr) asm volatile( \
  "ldmatrix.sync.aligned.m8n8.x4.shared.b16 {%0,%1,%2,%3}, [%4];\n" \
  : "=r"(r0), "=r"(r1), "=r"(r2), "=r"(r3) : "r"(addr))

__device__ __forceinline__ void split2(float x, float y, uint32_t& hi, uint32_t& lo)
{
    __nv_bfloat16 hx = __float2bfloat16(x);
    __nv_bfloat16 hy = __float2bfloat16(y);
    __nv_bfloat16 lx = __float2bfloat16(x - __bfloat162float(hx));
    __nv_bfloat16 ly = __float2bfloat16(y - __bfloat162float(hy));
    hi = (uint32_t)__bfloat16_as_ushort(hx) | ((uint32_t)__bfloat16_as_ushort(hy) << 16);
    lo = (uint32_t)__bfloat16_as_ushort(lx) | ((uint32_t)__bfloat16_as_ushort(ly) << 16);
}

// ---------------------------------------------------------------------------
// fp32 -> bf16 hi/lo split
// ---------------------------------------------------------------------------
__global__ void split_bf16(const float4* __restrict__ x,
                           uint2* __restrict__ hi, uint2* __restrict__ lo, int n4)
{
    int i = blockIdx.x * blockDim.x + threadIdx.x;
    if (i >= n4) return;
    float4 v = x[i];
    uint32_t h0, l0, h1, l1;
    split2(v.x, v.y, h0, l0);
    split2(v.z, v.w, h1, l1);
    hi[i] = make_uint2(h0, h1);
    lo[i] = make_uint2(l0, l1);
}

// ---------------------------------------------------------------------------
// NT GEMM: C = Ah*Bh^T + Ah*Bl^T + Al*Bh^T + bias
// CTA tile 128x128, BK=32, STATIC 40KB smem, ldmatrix.x4 fragment loads,
// REGISTER-PREFETCH pipeline: LDGs for chunk kc+1 issued before the MMA block
// of chunk kc (overlaps gmem latency with tensor work; no cp.async).
// 8 warps (2x4), warp tile 64x32.
// ---------------------------------------------------------------------------
#define GSTR 40    // smem row stride in bf16; ldmatrix row offsets i*80B mod 128 all distinct

__global__ __launch_bounds__(256) void gemm_bf16_mma(
    const __nv_bfloat16* __restrict__ Ah, const __nv_bfloat16* __restrict__ Al,
    const __nv_bfloat16* __restrict__ Bh, const __nv_bfloat16* __restrict__ Bl,
    const float* __restrict__ bias, float* __restrict__ C,
    int M, int N, int K)
{
    __shared__ __nv_bfloat16 sAh[128][GSTR], sAl[128][GSTR];
    __shared__ __nv_bfloat16 sBh[128][GSTR], sBl[128][GSTR];

    const int t    = threadIdx.x;
    const int lane = t & 31;
    const int warp = t >> 5;
    const int g    = lane >> 2;
    const int tg   = lane & 3;
    const int wm   = warp >> 2;
    const int wn   = warp & 3;
    const int bm   = blockIdx.x * 128, bn = blockIdx.y * 128;

    const int lr = t >> 1;            // 0..127
    const int lc = (t & 1) * 16;      // 0 or 16 (bf16)

    float acc[4][4][4] = {};

    const __nv_bfloat16* pAh = Ah + (size_t)(bm + lr) * K + lc;
    const __nv_bfloat16* pAl = Al + (size_t)(bm + lr) * K + lc;
    const __nv_bfloat16* pBh = Bh + (size_t)(bn + lr) * K + lc;
    const __nv_bfloat16* pBl = Bl + (size_t)(bn + lr) * K + lc;

    // ldmatrix per-lane address components
    const uint32_t aBase  = (uint32_t)__cvta_generic_to_shared(&sAh[0][0]);
    const uint32_t alBase = (uint32_t)__cvta_generic_to_shared(&sAl[0][0]);
    const uint32_t bBase  = (uint32_t)__cvta_generic_to_shared(&sBh[0][0]);
    const uint32_t blBase = (uint32_t)__cvta_generic_to_shared(&sBl[0][0]);
    const int arow = wm * 64 + (lane & 15);
    const int acol = (lane >> 4) * 8;
    const int brow = wn * 32 + (lane & 7) + ((lane >> 4) * 8);
    const int bcol = ((lane >> 3) & 1) * 8;

    // register staging for the gmem->smem pipeline
    uint4 rAh0, rAh1, rAl0, rAl1, rBh0, rBh1, rBl0, rBl1;
    auto ldreg = [&](int kc) {
        rAh0 = *(const uint4*)(pAh + kc);  rAh1 = *(const uint4*)(pAh + kc + 8);
        rAl0 = *(const uint4*)(pAl + kc);  rAl1 = *(const uint4*)(pAl + kc + 8);
        rBh0 = *(const uint4*)(pBh + kc);  rBh1 = *(const uint4*)(pBh + kc + 8);
        rBl0 = *(const uint4*)(pBl + kc);  rBl1 = *(const uint4*)(pBl + kc + 8);
    };
    ldreg(0);

    for (int kc = 0; kc < K; kc += 32) {
        // drain staged regs into smem
        *(uint4*)&sAh[lr][lc] = rAh0;  *(uint4*)&sAh[lr][lc + 8] = rAh1;
        *(uint4*)&sAl[lr][lc] = rAl0;  *(uint4*)&sAl[lr][lc + 8] = rAl1;
        *(uint4*)&sBh[lr][lc] = rBh0;  *(uint4*)&sBh[lr][lc + 8] = rBh1;
        *(uint4*)&sBl[lr][lc] = rBl0;  *(uint4*)&sBl[lr][lc + 8] = rBl1;
        __syncthreads();

        // issue next chunk's LDGs now; latency hides under the MMAs below
        if (kc + 32 < K) ldreg(kc + 32);

        #pragma unroll
        for (int ks = 0; ks < 2; ks++) {
            const int kof = ks * 16;
            uint32_t ah[4][4], al[4][4], bh[4][2], bl[4][2];
            #pragma unroll
            for (int mt = 0; mt < 4; mt++) {
                uint32_t off = (uint32_t)((arow + mt * 16) * GSTR + kof + acol) * 2;
                LDSM4(ah[mt][0], ah[mt][1], ah[mt][2], ah[mt][3], aBase + off);
                LDSM4(al[mt][0], al[mt][1], al[mt][2], al[mt][3], alBase + off);
            }
            #pragma unroll
            for (int np = 0; np < 2; np++) {
                uint32_t off = (uint32_t)((brow + np * 16) * GSTR + kof + bcol) * 2;
                LDSM4(bh[2*np][0], bh[2*np][1], bh[2*np+1][0], bh[2*np+1][1], bBase + off);
                LDSM4(bl[2*np][0], bl[2*np][1], bl[2*np+1][0], bl[2*np+1][1], blBase + off);
            }
            #pragma unroll
            for (int mt = 0; mt < 4; mt++)
                #pragma unroll
                for (int nt = 0; nt < 4; nt++) {
                    MMA_BF16(acc[mt][nt], ah[mt], bh[nt]);
                    MMA_BF16(acc[mt][nt], ah[mt], bl[nt]);
                    MMA_BF16(acc[mt][nt], al[mt], bh[nt]);
                }
        }
        __syncthreads();
    }

    // epilogue with bias
    #pragma unroll
    for (int mt = 0; mt < 4; mt++) {
        int row = bm + wm * 64 + mt * 16 + g;
        #pragma unroll
        for (int nt = 0; nt < 4; nt++) {
            int col = bn + wn * 32 + nt * 8 + tg * 2;
            float2 b2 = *(const float2*)&bias[col];
            float2 o0 = {acc[mt][nt][0] + b2.x, acc[mt][nt][1] + b2.y};
            float2 o1 = {acc[mt][nt][2] + b2.x, acc[mt][nt][3] + b2.y};
            *(float2*)&C[(size_t)row * N + col]       = o0;
            *(float2*)&C[(size_t)(row + 8) * N + col] = o1;
        }
    }
}

// ---------------------------------------------------------------------------
// Suffix sums of V per head (32 chunks of 64 rows)
// ---------------------------------------------------------------------------
__global__ void sfx1(const float* __restrict__ vp, float* __restrict__ sv,
                     float* __restrict__ csum)
{
    int g = blockIdx.x, c = blockIdx.y, d = threadIdx.x;
    const float* v = vp + (size_t)g * L_SEQ * HD;
    float* s = sv + (size_t)g * (L_SEQ + 1) * HD;
    float a = 0.f;
    #pragma unroll 8
    for (int j = (c + 1) * 64 - 1; j >= c * 64; j--) {
        a += v[j * HD + d];
        s[j * HD + d] = a;
    }
    csum[(g * 32 + c) * HD + d] = a;
}

__global__ void sfx2(float* __restrict__ sv, const float* __restrict__ csum)
{
    int g = blockIdx.x, c = blockIdx.y, d = threadIdx.x;
    float* s = sv + (size_t)g * (L_SEQ + 1) * HD;
    if (c == 31) { s[L_SEQ * HD + d] = 0.f; return; }
    float off = 0.f;
    for (int c2 = c + 1; c2 < 32; c2++) off += csum[(g * 32 + c2) * HD + d];
    #pragma unroll 8
    for (int j = c * 64; j < (c + 1) * 64; j++)
        s[j * HD + d] += off;
}

// ---------------------------------------------------------------------------
// Tensor-core flash attention (validated R10/R13). Unchanged.
// ---------------------------------------------------------------------------
#define ASTR 72

__global__ __launch_bounds__(128) void attn_mma(
    const float* __restrict__ qp, const float* __restrict__ kp,
    const float* __restrict__ vp, const float* __restrict__ sv,
    __nv_bfloat16* __restrict__ ch, __nv_bfloat16* __restrict__ cl)
{
    const int g  = blockIdx.y;
    const int qi = 31 - blockIdx.x;      // big tiles launch first
    const int i0 = qi * 64;
    const float* Qg = qp + (size_t)g * L_SEQ * HD;
    const float* Kg = kp + (size_t)g * L_SEQ * HD;
    const float* Vg = vp + (size_t)g * L_SEQ * HD;
    const float* svg = sv + (size_t)g * (L_SEQ + 1) * HD;

    __shared__ __nv_bfloat16 Kh[64][ASTR], Kl[64][ASTR];
    __shared__ __nv_bfloat16 Vh[64][ASTR], Vl[64][ASTR];   // transposed [d][key]

    const int t    = threadIdx.x;
    const int lane = t & 31;
    const int warp = t >> 5;
    const int gq   = lane >> 2;
    const int tg   = lane & 3;

    const int r0g = i0 + warp * 16 + gq;
    const int r1g = r0g + 8;

    // Q fragments -> registers
    uint32_t qah[4][4], qal[4][4];
    #pragma unroll
    for (int kc = 0; kc < 4; kc++) {
        const int kof = kc * 16 + tg * 2;
        float2 q00 = *(const float2*)&Qg[(size_t)r0g * HD + kof];
        float2 q10 = *(const float2*)&Qg[(size_t)r1g * HD + kof];
        float2 q01 = *(const float2*)&Qg[(size_t)r0g * HD + kof + 8];
        float2 q11 = *(const float2*)&Qg[(size_t)r1g * HD + kof + 8];
        split2(q00.x, q00.y, qah[kc][0], qal[kc][0]);
        split2(q10.x, q10.y, qah[kc][1], qal[kc][1]);
        split2(q01.x, q01.y, qah[kc][2], qal[kc][2]);
        split2(q11.x, q11.y, qah[kc][3], qal[kc][3]);
    }

    float oacc[8][4] = {};
    float m0 = -1e30f, m1 = -1e30f, l0s = 0.f, l1s = 0.f;

    for (int kb = 0; kb <= qi; kb++) {
        const int j0 = kb * 64;
        #pragma unroll
        for (int rep = 0; rep < 8; rep++) {
            int idx = t + rep * 128;
            int r = idx >> 4, d4 = (idx & 15) * 4;
            float4 kv = *(const float4*)&Kg[(size_t)(j0 + r) * HD + d4];
            uint32_t h0, l0, h1, l1;
            split2(kv.x, kv.y, h0, l0);
            split2(kv.z, kv.w, h1, l1);
            *(uint32_t*)&Kh[r][d4]     = h0;  *(uint32_t*)&Kh[r][d4 + 2] = h1;
            *(uint32_t*)&Kl[r][d4]     = l0;  *(uint32_t*)&Kl[r][d4 + 2] = l1;
            float4 vv = *(const float4*)&Vg[(size_t)(j0 + r) * HD + d4];
            float va[4] = {vv.x, vv.y, vv.z, vv.w};
            #pragma unroll
            for (int j = 0; j < 4; j++) {
                __nv_bfloat16 h = __float2bfloat16(va[j]);
                __nv_bfloat16 l = __float2bfloat16(va[j] - __bfloat162float(h));
                Vh[d4 + j][r] = h;
                Vl[d4 + j][r] = l;
            }
        }
        __syncthreads();

        float sacc[8][4] = {};
        #pragma unroll
        for (int kc = 0; kc < 4; kc++) {
            const int kof = kc * 16 + tg * 2;
            #pragma unroll
            for (int nt = 0; nt < 8; nt++) {
                uint32_t bh[2], bl[2];
                bh[0] = *(const uint32_t*)&Kh[nt * 8 + gq][kof];
                bh[1] = *(const uint32_t*)&Kh[nt * 8 + gq][kof + 8];
                bl[0] = *(const uint32_t*)&Kl[nt * 8 + gq][kof];
                bl[1] = *(const uint32_t*)&Kl[nt * 8 + gq][kof + 8];
                MMA_BF16(sacc[nt], qah[kc], bh);
                MMA_BF16(sacc[nt], qah[kc], bl);
                MMA_BF16(sacc[nt], qal[kc], bh);
            }
        }

        #pragma unroll
        for (int nt = 0; nt < 8; nt++) {
            int c0 = j0 + nt * 8 + tg * 2, c1 = c0 + 1;
            sacc[nt][0] = (c0 > r0g) ? -1e30f : sacc[nt][0] * 0.125f;
            sacc[nt][1] = (c1 > r0g) ? -1e30f : sacc[nt][1] * 0.125f;
            sacc[nt][2] = (c0 > r1g) ? -1e30f : sacc[nt][2] * 0.125f;
            sacc[nt][3] = (c1 > r1g) ? -1e30f : sacc[nt][3] * 0.125f;
        }

        float mx0 = -1e30f, mx1 = -1e30f;
        #pragma unroll
        for (int nt = 0; nt < 8; nt++) {
            mx0 = fmaxf(mx0, fmaxf(sacc[nt][0], sacc[nt][1]));
            mx1 = fmaxf(mx1, fmaxf(sacc[nt][2], sacc[nt][3]));
        }
        mx0 = fmaxf(mx0, __shfl_xor_sync(0xffffffffu, mx0, 1));
        mx0 = fmaxf(mx0, __shfl_xor_sync(0xffffffffu, mx0, 2));
        mx1 = fmaxf(mx1, __shfl_xor_sync(0xffffffffu, mx1, 1));
        mx1 = fmaxf(mx1, __shfl_xor_sync(0xffffffffu, mx1, 2));
        float mn0 = fmaxf(m0, mx0), mn1 = fmaxf(m1, mx1);
        float sc0 = __expf(m0 - mn0), sc1 = __expf(m1 - mn1);
        m0 = mn0; m1 = mn1;

        uint32_t pah[4][4], pal[4][4];
        float ls0 = 0.f, ls1 = 0.f;
        #pragma unroll
        for (int c = 0; c < 4; c++) {
            float p00 = __expf(sacc[2*c  ][0] - mn0), p01 = __expf(sacc[2*c  ][1] - mn0);
            float p10 = __expf(sacc[2*c  ][2] - mn1), p11 = __expf(sacc[2*c  ][3] - mn1);
            float p20 = __expf(sacc[2*c+1][0] - mn0), p21 = __expf(sacc[2*c+1][1] - mn0);
            float p30 = __expf(sacc[2*c+1][2] - mn1), p31 = __expf(sacc[2*c+1][3] - mn1);
            ls0 += p00 + p01 + p20 + p21;
            ls1 += p10 + p11 + p30 + p31;
            split2(p00, p01, pah[c][0], pal[c][0]);
            split2(p10, p11, pah[c][1], pal[c][1]);
            split2(p20, p21, pah[c][2], pal[c][2]);
            split2(p30, p31, pah[c][3], pal[c][3]);
        }
        ls0 += __shfl_xor_sync(0xffffffffu, ls0, 1);
        ls0 += __shfl_xor_sync(0xffffffffu, ls0, 2);
        ls1 += __shfl_xor_sync(0xffffffffu, ls1, 1);
        ls1 += __shfl_xor_sync(0xffffffffu, ls1, 2);
        l0s = l0s * sc0 + ls0;
        l1s = l1s * sc1 + ls1;

        #pragma unroll
        for (int dn = 0; dn < 8; dn++) {
            oacc[dn][0] *= sc0; oacc[dn][1] *= sc0;
            oacc[dn][2] *= sc1; oacc[dn][3] *= sc1;
        }

        #pragma unroll
        for (int c = 0; c < 4; c++) {
            const int kof = c * 16 + tg * 2;
            #pragma unroll
            for (int dn = 0; dn < 8; dn++) {
                uint32_t vh[2], vl[2];
                vh[0] = *(const uint32_t*)&Vh[dn * 8 + gq][kof];
                vh[1] = *(const uint32_t*)&Vh[dn * 8 + gq][kof + 8];
                vl[0] = *(const uint32_t*)&Vl[dn * 8 + gq][kof];
                vl[1] = *(const uint32_t*)&Vl[dn * 8 + gq][kof + 8];
                MMA_BF16(oacc[dn], pah[c], vh);
                MMA_BF16(oacc[dn], pah[c], vl);
                MMA_BF16(oacc[dn], pal[c], vh);
            }
        }
        __syncthreads();
    }

    float mf0 = fmaxf(m0, 0.f), mf1 = fmaxf(m1, 0.f);
    float ez0 = __expf(-mf0), ez1 = __expf(-mf1);
    float fc0 = __expf(m0 - mf0), fc1 = __expf(m1 - mf1);
    float inv0 = 1.f / (l0s * fc0 + (float)(L_SEQ - 1 - r0g) * ez0);
    float inv1 = 1.f / (l1s * fc1 + (float)(L_SEQ - 1 - r1g) * ez1);

    const size_t base = (size_t)g * L_SEQ * HD;
    #pragma unroll
    for (int dn = 0; dn < 8; dn++) {
        int d = dn * 8 + tg * 2;
        float2 s0 = *(const float2*)&svg[(size_t)(r0g + 1) * HD + d];
        float2 s1 = *(const float2*)&svg[(size_t)(r1g + 1) * HD + d];
        float o00 = (oacc[dn][0] * fc0 + ez0 * s0.x) * inv0;
        float o01 = (oacc[dn][1] * fc0 + ez0 * s0.y) * inv0;
        float o10 = (oacc[dn][2] * fc1 + ez1 * s1.x) * inv1;
        float o11 = (oacc[dn][3] * fc1 + ez1 * s1.y) * inv1;
        uint32_t h, l;
        split2(o00, o01, h, l);
        *(uint32_t*)&ch[base + (size_t)r0g * HD + d] = h;
        *(uint32_t*)&cl[base + (size_t)r0g * HD + d] = l;
        split2(o10, o11, h, l);
        *(uint32_t*)&ch[base + (size_t)r1g * HD + d] = h;
        *(uint32_t*)&cl[base + (size_t)r1g * HD + d] = l;
    }
}

// ---------------------------------------------------------------------------
extern "C" void kernel_launch(void* const* d_in, const int* in_sizes, int n_in,
                              void* d_out, int out_size)
{
    const float* q     = (const float*)d_in[0];
    const float* k     = (const float*)d_in[1];
    const float* v     = (const float*)d_in[2];
    // d_in[3] = attn_mask (causal by construction; handled analytically)
    const float* wq_w  = (const float*)d_in[4];
    const float* wq_b  = (const float*)d_in[5];
    const float* out_w = (const float*)d_in[6];
    const float* out_b = (const float*)d_in[7];
    float* out = (float*)d_out;

    float *qkvp, *sv, *csum;
    __nv_bfloat16 *ah, *al, *wh, *wl, *oh, *ol;
    cudaGetSymbolAddress((void**)&qkvp, g_qkvp);
    cudaGetSymbolAddress((void**)&sv,   g_sv);
    cudaGetSymbolAddress((void**)&csum, g_csum);
    cudaGetSymbolAddress((void**)&ah,   g_ah);
    cudaGetSymbolAddress((void**)&al,   g_al);
    cudaGetSymbolAddress((void**)&wh,   g_wh);
    cudaGetSymbolAddress((void**)&wl,   g_wl);
    cudaGetSymbolAddress((void**)&oh,   g_oh);
    cudaGetSymbolAddress((void**)&ol,   g_ol);

    const int NA4 = MTOT * DM / 4;
    const int NW4 = DM * DM / 4;
    const size_t MD = (size_t)MTOT * DM;

    float* qp = qkvp;
    float* kp = qkvp + MD;
    float* vp = qkvp + 2 * MD;

    // weight splits
    split_bf16<<<(NW4 + 255) / 256, 256>>>((const float4*)wq_w,  (uint2*)wh, (uint2*)wl, NW4);
    split_bf16<<<(NW4 + 255) / 256, 256>>>((const float4*)out_w, (uint2*)oh, (uint2*)ol, NW4);

    // input splits into one contiguous q|k|v buffer
    split_bf16<<<(NA4 + 255) / 256, 256>>>((const float4*)q,
        (uint2*)ah, (uint2*)al, NA4);
    split_bf16<<<(NA4 + 255) / 256, 256>>>((const float4*)k,
        (uint2*)(ah + MD), (uint2*)(al + MD), NA4);
    split_bf16<<<(NA4 + 255) / 256, 256>>>((const float4*)v,
        (uint2*)(ah + 2 * MD), (uint2*)(al + 2 * MD), NA4);

    // fused QKV projection: one GEMM, M = 3*4096
    gemm_bf16_mma<<<dim3(3 * MTOT / 128, DM / 128), 256>>>(
        ah, al, wh, wl, wq_b, qkvp, 3 * MTOT, DM, DM);

    sfx1<<<dim3(NG, 32), HD>>>(vp, sv, csum);
    sfx2<<<dim3(NG, 32), HD>>>(sv, csum);

    // tensor-core attention; writes ctx directly as bf16 hi/lo into ah/al
    attn_mma<<<dim3(L_SEQ / 64, NG), 128>>>(qp, kp, vp, sv, ah, al);

    // output projection
    gemm_bf16_mma<<<dim3(MTOT / 128, DM / 128), 256>>>(
        ah, al, oh, ol, out_b, out, MTOT, DM, DM);
}